// round 8
// baseline (speedup 1.0000x reference)
#include <cuda_runtime.h>
#include <math.h>
#include <stdint.h>

// Problem constants (fixed by the dataset)
#define T_TOK 4096
#define HID   1024
#define NE    16
#define FE    512
#define FS    2048
#define NPAIR (T_TOK * 2)

// ---------------------------------------------------------------------------
// Scratch
// ---------------------------------------------------------------------------
__device__ float g_gate_s[(size_t)T_TOK * FS];   // gate, then inter (in-place)
__device__ float g_gate_r[(size_t)NPAIR * FE];   // routed gate, then inter
__device__ float g_routed[(size_t)NPAIR * HID];
__device__ int   g_cnt[NE];
__device__ int   g_bucket[NE * T_TOK];
__device__ float g_pw[NPAIR];

// ---------------------------------------------------------------------------
// Router (validated rounds 1-7)
// ---------------------------------------------------------------------------
__global__ void zero_counts_kernel() {
    if (threadIdx.x < NE) g_cnt[threadIdx.x] = 0;
}

__global__ void router_kernel(const float* __restrict__ x,
                              const float* __restrict__ rw) {
    int warp = threadIdx.x >> 5;
    int lane = threadIdx.x & 31;
    int t = blockIdx.x * (blockDim.x >> 5) + warp;
    if (t >= T_TOK) return;

    float acc[NE];
#pragma unroll
    for (int e = 0; e < NE; e++) acc[e] = 0.0f;

    const float* xr = x + (size_t)t * HID;
    for (int d = lane; d < HID; d += 32) {
        float xv = xr[d];
        const float* r = rw + (size_t)d * NE;
#pragma unroll
        for (int e = 0; e < NE; e++) acc[e] = fmaf(xv, r[e], acc[e]);
    }
#pragma unroll
    for (int e = 0; e < NE; e++) {
#pragma unroll
        for (int off = 16; off; off >>= 1)
            acc[e] += __shfl_xor_sync(0xffffffffu, acc[e], off);
    }

    if (lane == 0) {
        float mx = acc[0];
#pragma unroll
        for (int e = 1; e < NE; e++) mx = fmaxf(mx, acc[e]);
        float p[NE];
        float s = 0.0f;
#pragma unroll
        for (int e = 0; e < NE; e++) { p[e] = expf(acc[e] - mx); s += p[e]; }
        float inv = 1.0f / s;
#pragma unroll
        for (int e = 0; e < NE; e++) p[e] *= inv;

        int   i0 = 0; float w0 = p[0];
#pragma unroll
        for (int e = 1; e < NE; e++) if (p[e] > w0) { w0 = p[e]; i0 = e; }
        int   i1 = -1; float w1 = -1.0f;
#pragma unroll
        for (int e = 0; e < NE; e++)
            if (e != i0 && p[e] > w1) { w1 = p[e]; i1 = e; }

        int pos0 = atomicAdd(&g_cnt[i0], 1);
        g_bucket[i0 * T_TOK + pos0] = 2 * t;
        int pos1 = atomicAdd(&g_cnt[i1], 1);
        g_bucket[i1 * T_TOK + pos1] = 2 * t + 1;
        g_pw[2 * t]     = w0;
        g_pw[2 * t + 1] = w1;
    }
}

// ---------------------------------------------------------------------------
// 3xTF32 split + mma.sync wrapper (validated; 3 terms REQUIRED for accuracy)
// ---------------------------------------------------------------------------
__device__ __forceinline__ void split_tf32(float v, uint32_t& hi, uint32_t& lo) {
    uint32_t h;
    asm("cvt.rna.tf32.f32 %0, %1;" : "=r"(h) : "f"(v));
    float r = v - __uint_as_float(h);
    uint32_t l;
    asm("cvt.rna.tf32.f32 %0, %1;" : "=r"(l) : "f"(r));
    hi = h; lo = l;
}

__device__ __forceinline__ void mma_tf32(float* d,
                                         const uint32_t* a,
                                         const uint32_t* b) {
    asm volatile(
        "mma.sync.aligned.m16n8k8.row.col.f32.tf32.tf32.f32 "
        "{%0,%1,%2,%3}, {%4,%5,%6,%7}, {%8,%9}, {%0,%1,%2,%3};\n"
        : "+f"(d[0]), "+f"(d[1]), "+f"(d[2]), "+f"(d[3])
        : "r"(a[0]), "r"(a[1]), "r"(a[2]), "r"(a[3]),
          "r"(b[0]), "r"(b[1]));
}

// ---------------------------------------------------------------------------
// Tensor GEMM 128x64x16, 256 threads (8 warps as 4x2, warp tile 32x32),
// producer-side hi/lo split, 3 CTAs/SM target.
// Smem (per stage, words): Ah [128][20] @0, Al @2560,
//                          Bh [16][72]  @5120, Bl @6272; stage 7424 w.
// MODE 0: plain. MODE 1: gather x rows by pair>>1, scatter C by pair.
// MODE 2: gather rows by pair, scale C by router weight, scatter by pair.
// FUSE 1: C[..] = silu(G[..]) * acc.
// ---------------------------------------------------------------------------
#define BM 128
#define BN 64
#define BK 16
#define A_PAD 20
#define B_PAD 72
#define OFF_AL 2560
#define OFF_BH 5120
#define OFF_BL 6272
#define STAGEF 7424
#define SMEM_DYN (2 * STAGEF * 4)

template <int MODE, int FUSE>
__global__ __launch_bounds__(256, 3)
void tgemm_kernel(const float* __restrict__ A,
                  const float* __restrict__ B,
                  float* __restrict__ C,
                  const float* __restrict__ G,
                  int M, int N, int K) {
    int e = blockIdx.z;
    int m_rows = M;
    const int* rowlist = nullptr;
    if (MODE != 0) {
        m_rows  = g_cnt[e];
        rowlist = g_bucket + e * T_TOK;
        B += (size_t)e * K * N;
    }
    const int m0 = blockIdx.y * BM;
    const int n0 = blockIdx.x * BN;
    if (m0 >= m_rows) return;

    extern __shared__ uint32_t sm[];

    const int tid  = threadIdx.x;
    const int lane = tid & 31;
    const int wid  = tid >> 5;
    const int warp_m = wid >> 1;          // 0..3
    const int warp_n = wid & 1;           // 0..1
    const int g  = lane >> 2;             // 0..7
    const int t4 = lane & 3;              // 0..3
    const int mb = warp_m * 32;
    const int nb = warp_n * 32;

    // --- loader mappings ---
    // A (128x16): m = tid>>1, k-octet = (tid&1)*8  (validated R4)
    const int am  = tid >> 1;
    const int akq = (tid & 1) * 8;
    // B (16x64): row = tid>>4 (0..15), col quad = (tid&15)*4
    const int bkr = tid >> 4;
    const int bn4 = (tid & 15) * 4;

    const int  ar_g = m0 + am;
    const bool av   = ar_g < m_rows;
    const int  aidx = av ? ar_g : 0;
    const float* Arow;
    if (MODE == 0)      Arow = A + (size_t)aidx * K;
    else if (MODE == 1) Arow = A + (size_t)(rowlist[aidx] >> 1) * K;
    else                Arow = A + (size_t)rowlist[aidx] * K;

    const float* Bp = B + (size_t)bkr * N + n0 + bn4;

    auto stage_store = [&](int s, float4 va0, float4 va1, float4 vb) {
        uint32_t* st = sm + s * STAGEF;
        uint32_t h0, l0, h1, l1, h2, l2, h3, l3;
        split_tf32(va0.x, h0, l0); split_tf32(va0.y, h1, l1);
        split_tf32(va0.z, h2, l2); split_tf32(va0.w, h3, l3);
        *(uint4*)(st + am * A_PAD + akq)          = make_uint4(h0, h1, h2, h3);
        *(uint4*)(st + OFF_AL + am * A_PAD + akq) = make_uint4(l0, l1, l2, l3);
        split_tf32(va1.x, h0, l0); split_tf32(va1.y, h1, l1);
        split_tf32(va1.z, h2, l2); split_tf32(va1.w, h3, l3);
        *(uint4*)(st + am * A_PAD + akq + 4)          = make_uint4(h0, h1, h2, h3);
        *(uint4*)(st + OFF_AL + am * A_PAD + akq + 4) = make_uint4(l0, l1, l2, l3);
        split_tf32(vb.x, h0, l0); split_tf32(vb.y, h1, l1);
        split_tf32(vb.z, h2, l2); split_tf32(vb.w, h3, l3);
        *(uint4*)(st + OFF_BH + bkr * B_PAD + bn4) = make_uint4(h0, h1, h2, h3);
        *(uint4*)(st + OFF_BL + bkr * B_PAD + bn4) = make_uint4(l0, l1, l2, l3);
    };

    // Prefetch stage 0
    {
        float4 va0 = make_float4(0, 0, 0, 0), va1 = va0;
        if (av) {
            va0 = *(const float4*)(Arow + akq);
            va1 = *(const float4*)(Arow + akq + 4);
        }
        float4 vb = *(const float4*)Bp;
        stage_store(0, va0, va1, vb);
    }
    __syncthreads();

    float acc[2][4][4];
#pragma unroll
    for (int i = 0; i < 2; i++)
#pragma unroll
        for (int j = 0; j < 4; j++)
#pragma unroll
            for (int r = 0; r < 4; r++) acc[i][j][r] = 0.0f;

    const int KT = K / BK;
    float4 va0, va1, vb;

    for (int kt = 0; kt < KT; kt++) {
        const int cur = kt & 1;
        if (kt + 1 < KT) {
            const int k0 = (kt + 1) * BK;
            va0 = make_float4(0, 0, 0, 0); va1 = va0;
            if (av) {
                va0 = *(const float4*)(Arow + k0 + akq);
                va1 = *(const float4*)(Arow + k0 + akq + 4);
            }
            vb = *(const float4*)(Bp + (size_t)k0 * N);
        }

        const uint32_t* Ah = sm + cur * STAGEF;
        const uint32_t* Al = Ah + OFF_AL;
        const uint32_t* Bh = sm + cur * STAGEF + OFF_BH;
        const uint32_t* Bl = Bh + (OFF_BL - OFF_BH);

#pragma unroll
        for (int kk = 0; kk < BK; kk += 8) {
            uint32_t bh[4][2], bl[4][2];
#pragma unroll
            for (int nt = 0; nt < 4; nt++) {
                const int col = nb + nt * 8 + g;
                bh[nt][0] = Bh[(kk + t4) * B_PAD + col];
                bh[nt][1] = Bh[(kk + t4 + 4) * B_PAD + col];
                bl[nt][0] = Bl[(kk + t4) * B_PAD + col];
                bl[nt][1] = Bl[(kk + t4 + 4) * B_PAD + col];
            }
#pragma unroll
            for (int mt = 0; mt < 2; mt++) {
                const int r0 = (mb + mt * 16 + g) * A_PAD;
                const int r1 = r0 + 8 * A_PAD;
                uint32_t ah[4], al[4];
                ah[0] = Ah[r0 + kk + t4];
                ah[1] = Ah[r1 + kk + t4];
                ah[2] = Ah[r0 + kk + t4 + 4];
                ah[3] = Ah[r1 + kk + t4 + 4];
                al[0] = Al[r0 + kk + t4];
                al[1] = Al[r1 + kk + t4];
                al[2] = Al[r0 + kk + t4 + 4];
                al[3] = Al[r1 + kk + t4 + 4];
#pragma unroll
                for (int nt = 0; nt < 4; nt++) {
                    mma_tf32(acc[mt][nt], ah, bh[nt]);
                    mma_tf32(acc[mt][nt], ah, bl[nt]);
                    mma_tf32(acc[mt][nt], al, bh[nt]);
                }
            }
        }

        if (kt + 1 < KT) stage_store(cur ^ 1, va0, va1, vb);
        __syncthreads();
    }

    // Epilogue (+ optional silu(G)*acc fusion)
#pragma unroll
    for (int mt = 0; mt < 2; mt++) {
        const int r0 = m0 + mb + mt * 16 + g;
        const int r1 = r0 + 8;
        float* Crow0 = nullptr; float* Crow1 = nullptr;
        const float* Grow0 = nullptr; const float* Grow1 = nullptr;
        float s0 = 1.0f, s1 = 1.0f;
        if (r0 < m_rows) {
            size_t ro;
            if (MODE == 0) ro = (size_t)r0 * N;
            else {
                const int p = rowlist[r0];
                ro = (size_t)p * N;
                if (MODE == 2) s0 = g_pw[p];
            }
            Crow0 = C + ro;
            if (FUSE) Grow0 = G + ro;
        }
        if (r1 < m_rows) {
            size_t ro;
            if (MODE == 0) ro = (size_t)r1 * N;
            else {
                const int p = rowlist[r1];
                ro = (size_t)p * N;
                if (MODE == 2) s1 = g_pw[p];
            }
            Crow1 = C + ro;
            if (FUSE) Grow1 = G + ro;
        }
#pragma unroll
        for (int nt = 0; nt < 4; nt++) {
            const int c = n0 + nb + nt * 8 + 2 * t4;
            if (Crow0) {
                float o0 = acc[mt][nt][0] * s0, o1 = acc[mt][nt][1] * s0;
                if (FUSE) {
                    float2 gv = *(const float2*)(Grow0 + c);
                    o0 *= gv.x / (1.0f + expf(-gv.x));
                    o1 *= gv.y / (1.0f + expf(-gv.y));
                }
                *(float2*)(Crow0 + c) = make_float2(o0, o1);
            }
            if (Crow1) {
                float o0 = acc[mt][nt][2] * s1, o1 = acc[mt][nt][3] * s1;
                if (FUSE) {
                    float2 gv = *(const float2*)(Grow1 + c);
                    o0 *= gv.x / (1.0f + expf(-gv.x));
                    o1 *= gv.y / (1.0f + expf(-gv.y));
                }
                *(float2*)(Crow1 + c) = make_float2(o0, o1);
            }
        }
    }
}

// ---------------------------------------------------------------------------
// Final: out[t] += routed[2t] + routed[2t+1]
// ---------------------------------------------------------------------------
__global__ void final_add_kernel(float* __restrict__ out) {
    int i = blockIdx.x * blockDim.x + threadIdx.x;
    if (i >= T_TOK * HID / 4) return;
    const int t  = i >> 8;
    const int d4 = i & 255;
    float4 o = ((const float4*)out)[i];
    float4 a = ((const float4*)(g_routed + (size_t)(2 * t) * HID))[d4];
    float4 b = ((const float4*)(g_routed + (size_t)(2 * t + 1) * HID))[d4];
    o.x += a.x + b.x;
    o.y += a.y + b.y;
    o.z += a.z + b.z;
    o.w += a.w + b.w;
    ((float4*)out)[i] = o;
}

// ---------------------------------------------------------------------------
// Launch
// ---------------------------------------------------------------------------
extern "C" void kernel_launch(void* const* d_in, const int* in_sizes, int n_in,
                              void* d_out, int out_size) {
    const float* x  = (const float*)d_in[0];
    const float* rw = (const float*)d_in[1];
    const float* eg = (const float*)d_in[2];
    const float* eu = (const float*)d_in[3];
    const float* ed = (const float*)d_in[4];
    const float* sg = (const float*)d_in[5];
    const float* su = (const float*)d_in[6];
    const float* sd = (const float*)d_in[7];
    float* out = (float*)d_out;

    void *p_gate_s, *p_gate_r, *p_routed;
    cudaGetSymbolAddress(&p_gate_s, g_gate_s);
    cudaGetSymbolAddress(&p_gate_r, g_gate_r);
    cudaGetSymbolAddress(&p_routed, g_routed);

    cudaFuncSetAttribute(tgemm_kernel<0, 0>,
                         cudaFuncAttributeMaxDynamicSharedMemorySize, SMEM_DYN);
    cudaFuncSetAttribute(tgemm_kernel<0, 1>,
                         cudaFuncAttributeMaxDynamicSharedMemorySize, SMEM_DYN);
    cudaFuncSetAttribute(tgemm_kernel<1, 0>,
                         cudaFuncAttributeMaxDynamicSharedMemorySize, SMEM_DYN);
    cudaFuncSetAttribute(tgemm_kernel<1, 1>,
                         cudaFuncAttributeMaxDynamicSharedMemorySize, SMEM_DYN);
    cudaFuncSetAttribute(tgemm_kernel<2, 0>,
                         cudaFuncAttributeMaxDynamicSharedMemorySize, SMEM_DYN);

    zero_counts_kernel<<<1, 32>>>();
    router_kernel<<<T_TOK / 4, 128>>>(x, rw);

    // Shared expert: gate -> (up, silu fused) -> down
    tgemm_kernel<0, 0><<<dim3(FS / BN, T_TOK / BM, 1), 256, SMEM_DYN>>>(
        x, sg, (float*)p_gate_s, nullptr, T_TOK, FS, HID);
    tgemm_kernel<0, 1><<<dim3(FS / BN, T_TOK / BM, 1), 256, SMEM_DYN>>>(
        x, su, (float*)p_gate_s, (const float*)p_gate_s, T_TOK, FS, HID);
    tgemm_kernel<0, 0><<<dim3(HID / BN, T_TOK / BM, 1), 256, SMEM_DYN>>>(
        (const float*)p_gate_s, sd, out, nullptr, T_TOK, HID, FS);

    // Routed experts: gate -> (up, silu fused) -> down (scaled scatter)
    tgemm_kernel<1, 0><<<dim3(FE / BN, T_TOK / BM, NE), 256, SMEM_DYN>>>(
        x, eg, (float*)p_gate_r, nullptr, 0, FE, HID);
    tgemm_kernel<1, 1><<<dim3(FE / BN, T_TOK / BM, NE), 256, SMEM_DYN>>>(
        x, eu, (float*)p_gate_r, (const float*)p_gate_r, 0, FE, HID);
    tgemm_kernel<2, 0><<<dim3(HID / BN, T_TOK / BM, NE), 256, SMEM_DYN>>>(
        (const float*)p_gate_r, ed, (float*)p_routed, nullptr, 0, HID, FE);

    final_add_kernel<<<(T_TOK * HID / 4) / 256, 256>>>(out);
}

// round 9
// speedup vs baseline: 1.1841x; 1.1841x over previous
#include <cuda_runtime.h>
#include <math.h>
#include <stdint.h>

// Problem constants (fixed by the dataset)
#define T_TOK 4096
#define HID   1024
#define NE    16
#define FE    512
#define FS    2048
#define NPAIR (T_TOK * 2)

// ---------------------------------------------------------------------------
// Scratch
// ---------------------------------------------------------------------------
__device__ float g_gate_s[(size_t)T_TOK * FS];   // gate, then inter (in-place)
__device__ float g_gate_r[(size_t)NPAIR * FE];   // routed gate, then inter
__device__ float g_routed[(size_t)NPAIR * HID];
__device__ int   g_cnt[NE];
__device__ int   g_bucket[NE * T_TOK];
__device__ float g_pw[NPAIR];

// ---------------------------------------------------------------------------
// Router (validated rounds 1-8)
// ---------------------------------------------------------------------------
__global__ void zero_counts_kernel() {
    if (threadIdx.x < NE) g_cnt[threadIdx.x] = 0;
}

__global__ void router_kernel(const float* __restrict__ x,
                              const float* __restrict__ rw) {
    int warp = threadIdx.x >> 5;
    int lane = threadIdx.x & 31;
    int t = blockIdx.x * (blockDim.x >> 5) + warp;
    if (t >= T_TOK) return;

    float acc[NE];
#pragma unroll
    for (int e = 0; e < NE; e++) acc[e] = 0.0f;

    const float* xr = x + (size_t)t * HID;
    for (int d = lane; d < HID; d += 32) {
        float xv = xr[d];
        const float* r = rw + (size_t)d * NE;
#pragma unroll
        for (int e = 0; e < NE; e++) acc[e] = fmaf(xv, r[e], acc[e]);
    }
#pragma unroll
    for (int e = 0; e < NE; e++) {
#pragma unroll
        for (int off = 16; off; off >>= 1)
            acc[e] += __shfl_xor_sync(0xffffffffu, acc[e], off);
    }

    if (lane == 0) {
        float mx = acc[0];
#pragma unroll
        for (int e = 1; e < NE; e++) mx = fmaxf(mx, acc[e]);
        float p[NE];
        float s = 0.0f;
#pragma unroll
        for (int e = 0; e < NE; e++) { p[e] = expf(acc[e] - mx); s += p[e]; }
        float inv = 1.0f / s;
#pragma unroll
        for (int e = 0; e < NE; e++) p[e] *= inv;

        int   i0 = 0; float w0 = p[0];
#pragma unroll
        for (int e = 1; e < NE; e++) if (p[e] > w0) { w0 = p[e]; i0 = e; }
        int   i1 = -1; float w1 = -1.0f;
#pragma unroll
        for (int e = 0; e < NE; e++)
            if (e != i0 && p[e] > w1) { w1 = p[e]; i1 = e; }

        int pos0 = atomicAdd(&g_cnt[i0], 1);
        g_bucket[i0 * T_TOK + pos0] = 2 * t;
        int pos1 = atomicAdd(&g_cnt[i1], 1);
        g_bucket[i1 * T_TOK + pos1] = 2 * t + 1;
        g_pw[2 * t]     = w0;
        g_pw[2 * t + 1] = w1;
    }
}

// ---------------------------------------------------------------------------
// 3xTF32 split + mma.sync wrapper (validated; 3 terms REQUIRED for accuracy)
// ---------------------------------------------------------------------------
__device__ __forceinline__ void split_tf32(float v, uint32_t& hi, uint32_t& lo) {
    uint32_t h;
    asm("cvt.rna.tf32.f32 %0, %1;" : "=r"(h) : "f"(v));
    float r = v - __uint_as_float(h);
    uint32_t l;
    asm("cvt.rna.tf32.f32 %0, %1;" : "=r"(l) : "f"(r));
    hi = h; lo = l;
}

__device__ __forceinline__ void mma_tf32(float* d,
                                         const uint32_t* a,
                                         const uint32_t* b) {
    asm volatile(
        "mma.sync.aligned.m16n8k8.row.col.f32.tf32.tf32.f32 "
        "{%0,%1,%2,%3}, {%4,%5,%6,%7}, {%8,%9}, {%0,%1,%2,%3};\n"
        : "+f"(d[0]), "+f"(d[1]), "+f"(d[2]), "+f"(d[3])
        : "r"(a[0]), "r"(a[1]), "r"(a[2]), "r"(a[3]),
          "r"(b[0]), "r"(b[1]));
}

// ---------------------------------------------------------------------------
// Tensor GEMM 128x128x16, 256 threads, producer-side hi/lo split.
// R7 structure; ONLY change: term-major MMA ordering (dependency dist 1->4).
//   Ah: [128][20] off 0, Al: off 2560, Bh: [16][136] off 5120, Bl: off 7296
// MODE 0: plain. MODE 1: gather x rows by pair>>1, scatter C by pair.
// MODE 2: gather rows by pair, scale C by router weight, scatter by pair.
// FUSE 1: C[..] = silu(G[..]) * acc.
// ---------------------------------------------------------------------------
#define BM 128
#define BN 128
#define BK 16
#define A_PAD 20
#define B_PAD 136
#define OFF_AL 2560
#define OFF_BH 5120
#define OFF_BL 7296
#define STAGEF 9472
#define SMEM_DYN (2 * STAGEF * 4)

template <int MODE, int FUSE>
__global__ __launch_bounds__(256, 2)
void tgemm_kernel(const float* __restrict__ A,
                  const float* __restrict__ B,
                  float* __restrict__ C,
                  const float* __restrict__ G,
                  int M, int N, int K) {
    int e = blockIdx.z;
    int m_rows = M;
    const int* rowlist = nullptr;
    if (MODE != 0) {
        m_rows  = g_cnt[e];
        rowlist = g_bucket + e * T_TOK;
        B += (size_t)e * K * N;
    }
    const int m0 = blockIdx.y * BM;
    const int n0 = blockIdx.x * BN;
    if (m0 >= m_rows) return;

    extern __shared__ uint32_t sm[];

    const int tid  = threadIdx.x;
    const int lane = tid & 31;
    const int wid  = tid >> 5;
    const int warp_m = wid >> 2;          // 0..1
    const int warp_n = wid & 3;           // 0..3
    const int g  = lane >> 2;             // 0..7
    const int t4 = lane & 3;              // 0..3
    const int mb = warp_m * 64;
    const int nb = warp_n * 32;

    // --- loader mappings (validated R4/R7) ---
    const int am  = tid >> 1;
    const int akq = (tid & 1) * 8;
    const int bkr = tid >> 5;
    const int bn4 = (tid & 31) * 4;

    const int  ar_g = m0 + am;
    const bool av   = ar_g < m_rows;
    const int  aidx = av ? ar_g : 0;
    const float* Arow;
    if (MODE == 0)      Arow = A + (size_t)aidx * K;
    else if (MODE == 1) Arow = A + (size_t)(rowlist[aidx] >> 1) * K;
    else                Arow = A + (size_t)rowlist[aidx] * K;

    const float* Bp0 = B + (size_t)bkr * N + n0 + bn4;
    const float* Bp1 = B + (size_t)(bkr + 8) * N + n0 + bn4;

    auto stage_store = [&](int s, float4 va0, float4 va1, float4 vb0, float4 vb1) {
        uint32_t* st = sm + s * STAGEF;
        uint32_t h0, l0, h1, l1, h2, l2, h3, l3;
        split_tf32(va0.x, h0, l0); split_tf32(va0.y, h1, l1);
        split_tf32(va0.z, h2, l2); split_tf32(va0.w, h3, l3);
        *(uint4*)(st + am * A_PAD + akq)          = make_uint4(h0, h1, h2, h3);
        *(uint4*)(st + OFF_AL + am * A_PAD + akq) = make_uint4(l0, l1, l2, l3);
        split_tf32(va1.x, h0, l0); split_tf32(va1.y, h1, l1);
        split_tf32(va1.z, h2, l2); split_tf32(va1.w, h3, l3);
        *(uint4*)(st + am * A_PAD + akq + 4)          = make_uint4(h0, h1, h2, h3);
        *(uint4*)(st + OFF_AL + am * A_PAD + akq + 4) = make_uint4(l0, l1, l2, l3);
        split_tf32(vb0.x, h0, l0); split_tf32(vb0.y, h1, l1);
        split_tf32(vb0.z, h2, l2); split_tf32(vb0.w, h3, l3);
        *(uint4*)(st + OFF_BH + bkr * B_PAD + bn4) = make_uint4(h0, h1, h2, h3);
        *(uint4*)(st + OFF_BL + bkr * B_PAD + bn4) = make_uint4(l0, l1, l2, l3);
        split_tf32(vb1.x, h0, l0); split_tf32(vb1.y, h1, l1);
        split_tf32(vb1.z, h2, l2); split_tf32(vb1.w, h3, l3);
        *(uint4*)(st + OFF_BH + (bkr + 8) * B_PAD + bn4) = make_uint4(h0, h1, h2, h3);
        *(uint4*)(st + OFF_BL + (bkr + 8) * B_PAD + bn4) = make_uint4(l0, l1, l2, l3);
    };

    // Prefetch stage 0
    {
        float4 va0 = make_float4(0, 0, 0, 0), va1 = va0;
        if (av) {
            va0 = *(const float4*)(Arow + akq);
            va1 = *(const float4*)(Arow + akq + 4);
        }
        float4 vb0 = *(const float4*)Bp0;
        float4 vb1 = *(const float4*)Bp1;
        stage_store(0, va0, va1, vb0, vb1);
    }
    __syncthreads();

    float acc[4][4][4];
#pragma unroll
    for (int i = 0; i < 4; i++)
#pragma unroll
        for (int j = 0; j < 4; j++)
#pragma unroll
            for (int r = 0; r < 4; r++) acc[i][j][r] = 0.0f;

    const int KT = K / BK;
    float4 va0, va1, vb0, vb1;

    for (int kt = 0; kt < KT; kt++) {
        const int cur = kt & 1;
        if (kt + 1 < KT) {
            const int k0 = (kt + 1) * BK;
            va0 = make_float4(0, 0, 0, 0); va1 = va0;
            if (av) {
                va0 = *(const float4*)(Arow + k0 + akq);
                va1 = *(const float4*)(Arow + k0 + akq + 4);
            }
            vb0 = *(const float4*)(Bp0 + (size_t)k0 * N);
            vb1 = *(const float4*)(Bp1 + (size_t)k0 * N);
        }

        const uint32_t* Ah = sm + cur * STAGEF;
        const uint32_t* Al = Ah + OFF_AL;
        const uint32_t* Bh = sm + cur * STAGEF + OFF_BH;
        const uint32_t* Bl = Bh + (OFF_BL - OFF_BH);

#pragma unroll
        for (int kk = 0; kk < BK; kk += 8) {
            uint32_t bh[4][2], bl[4][2];
#pragma unroll
            for (int nt = 0; nt < 4; nt++) {
                const int col = nb + nt * 8 + g;
                bh[nt][0] = Bh[(kk + t4) * B_PAD + col];
                bh[nt][1] = Bh[(kk + t4 + 4) * B_PAD + col];
                bl[nt][0] = Bl[(kk + t4) * B_PAD + col];
                bl[nt][1] = Bl[(kk + t4 + 4) * B_PAD + col];
            }
#pragma unroll
            for (int mt = 0; mt < 4; mt++) {
                const int r0 = (mb + mt * 16 + g) * A_PAD;
                const int r1 = r0 + 8 * A_PAD;
                uint32_t ah[4], al[4];
                ah[0] = Ah[r0 + kk + t4];
                ah[1] = Ah[r1 + kk + t4];
                ah[2] = Ah[r0 + kk + t4 + 4];
                ah[3] = Ah[r1 + kk + t4 + 4];
                al[0] = Al[r0 + kk + t4];
                al[1] = Al[r1 + kk + t4];
                al[2] = Al[r0 + kk + t4 + 4];
                al[3] = Al[r1 + kk + t4 + 4];
                // Term-major ordering: 4 independent accumulators per term,
                // RAW distance on each acc = 4 MMAs (was 1).
#pragma unroll
                for (int nt = 0; nt < 4; nt++) mma_tf32(acc[mt][nt], ah, bh[nt]);
#pragma unroll
                for (int nt = 0; nt < 4; nt++) mma_tf32(acc[mt][nt], ah, bl[nt]);
#pragma unroll
                for (int nt = 0; nt < 4; nt++) mma_tf32(acc[mt][nt], al, bh[nt]);
            }
        }

        if (kt + 1 < KT) stage_store(cur ^ 1, va0, va1, vb0, vb1);
        __syncthreads();
    }

    // Epilogue (+ optional silu(G)*acc fusion)
#pragma unroll
    for (int mt = 0; mt < 4; mt++) {
        const int r0 = m0 + mb + mt * 16 + g;
        const int r1 = r0 + 8;
        float* Crow0 = nullptr; float* Crow1 = nullptr;
        const float* Grow0 = nullptr; const float* Grow1 = nullptr;
        float s0 = 1.0f, s1 = 1.0f;
        if (r0 < m_rows) {
            size_t ro;
            if (MODE == 0) ro = (size_t)r0 * N;
            else {
                const int p = rowlist[r0];
                ro = (size_t)p * N;
                if (MODE == 2) s0 = g_pw[p];
            }
            Crow0 = C + ro;
            if (FUSE) Grow0 = G + ro;
        }
        if (r1 < m_rows) {
            size_t ro;
            if (MODE == 0) ro = (size_t)r1 * N;
            else {
                const int p = rowlist[r1];
                ro = (size_t)p * N;
                if (MODE == 2) s1 = g_pw[p];
            }
            Crow1 = C + ro;
            if (FUSE) Grow1 = G + ro;
        }
#pragma unroll
        for (int nt = 0; nt < 4; nt++) {
            const int c = n0 + nb + nt * 8 + 2 * t4;
            if (Crow0) {
                float o0 = acc[mt][nt][0] * s0, o1 = acc[mt][nt][1] * s0;
                if (FUSE) {
                    float2 gv = *(const float2*)(Grow0 + c);
                    o0 *= gv.x / (1.0f + expf(-gv.x));
                    o1 *= gv.y / (1.0f + expf(-gv.y));
                }
                *(float2*)(Crow0 + c) = make_float2(o0, o1);
            }
            if (Crow1) {
                float o0 = acc[mt][nt][2] * s1, o1 = acc[mt][nt][3] * s1;
                if (FUSE) {
                    float2 gv = *(const float2*)(Grow1 + c);
                    o0 *= gv.x / (1.0f + expf(-gv.x));
                    o1 *= gv.y / (1.0f + expf(-gv.y));
                }
                *(float2*)(Crow1 + c) = make_float2(o0, o1);
            }
        }
    }
}

// ---------------------------------------------------------------------------
// Final: out[t] += routed[2t] + routed[2t+1]
// ---------------------------------------------------------------------------
__global__ void final_add_kernel(float* __restrict__ out) {
    int i = blockIdx.x * blockDim.x + threadIdx.x;
    if (i >= T_TOK * HID / 4) return;
    const int t  = i >> 8;
    const int d4 = i & 255;
    float4 o = ((const float4*)out)[i];
    float4 a = ((const float4*)(g_routed + (size_t)(2 * t) * HID))[d4];
    float4 b = ((const float4*)(g_routed + (size_t)(2 * t + 1) * HID))[d4];
    o.x += a.x + b.x;
    o.y += a.y + b.y;
    o.z += a.z + b.z;
    o.w += a.w + b.w;
    ((float4*)out)[i] = o;
}

// ---------------------------------------------------------------------------
// Launch
// ---------------------------------------------------------------------------
extern "C" void kernel_launch(void* const* d_in, const int* in_sizes, int n_in,
                              void* d_out, int out_size) {
    const float* x  = (const float*)d_in[0];
    const float* rw = (const float*)d_in[1];
    const float* eg = (const float*)d_in[2];
    const float* eu = (const float*)d_in[3];
    const float* ed = (const float*)d_in[4];
    const float* sg = (const float*)d_in[5];
    const float* su = (const float*)d_in[6];
    const float* sd = (const float*)d_in[7];
    float* out = (float*)d_out;

    void *p_gate_s, *p_gate_r, *p_routed;
    cudaGetSymbolAddress(&p_gate_s, g_gate_s);
    cudaGetSymbolAddress(&p_gate_r, g_gate_r);
    cudaGetSymbolAddress(&p_routed, g_routed);

    cudaFuncSetAttribute(tgemm_kernel<0, 0>,
                         cudaFuncAttributeMaxDynamicSharedMemorySize, SMEM_DYN);
    cudaFuncSetAttribute(tgemm_kernel<0, 1>,
                         cudaFuncAttributeMaxDynamicSharedMemorySize, SMEM_DYN);
    cudaFuncSetAttribute(tgemm_kernel<1, 0>,
                         cudaFuncAttributeMaxDynamicSharedMemorySize, SMEM_DYN);
    cudaFuncSetAttribute(tgemm_kernel<1, 1>,
                         cudaFuncAttributeMaxDynamicSharedMemorySize, SMEM_DYN);
    cudaFuncSetAttribute(tgemm_kernel<2, 0>,
                         cudaFuncAttributeMaxDynamicSharedMemorySize, SMEM_DYN);

    zero_counts_kernel<<<1, 32>>>();
    router_kernel<<<T_TOK / 4, 128>>>(x, rw);

    // Shared expert: gate -> (up, silu fused) -> down
    tgemm_kernel<0, 0><<<dim3(FS / BN, T_TOK / BM, 1), 256, SMEM_DYN>>>(
        x, sg, (float*)p_gate_s, nullptr, T_TOK, FS, HID);
    tgemm_kernel<0, 1><<<dim3(FS / BN, T_TOK / BM, 1), 256, SMEM_DYN>>>(
        x, su, (float*)p_gate_s, (const float*)p_gate_s, T_TOK, FS, HID);
    tgemm_kernel<0, 0><<<dim3(HID / BN, T_TOK / BM, 1), 256, SMEM_DYN>>>(
        (const float*)p_gate_s, sd, out, nullptr, T_TOK, HID, FS);

    // Routed experts: gate -> (up, silu fused) -> down (scaled scatter)
    tgemm_kernel<1, 0><<<dim3(FE / BN, T_TOK / BM, NE), 256, SMEM_DYN>>>(
        x, eg, (float*)p_gate_r, nullptr, 0, FE, HID);
    tgemm_kernel<1, 1><<<dim3(FE / BN, T_TOK / BM, NE), 256, SMEM_DYN>>>(
        x, eu, (float*)p_gate_r, (const float*)p_gate_r, 0, FE, HID);
    tgemm_kernel<2, 0><<<dim3(HID / BN, T_TOK / BM, NE), 256, SMEM_DYN>>>(
        (const float*)p_gate_r, ed, (float*)p_routed, nullptr, 0, HID, FE);

    final_add_kernel<<<(T_TOK * HID / 4) / 256, 256>>>(out);
}

// round 10
// speedup vs baseline: 1.3941x; 1.1773x over previous
#include <cuda_runtime.h>
#include <cuda_fp16.h>
#include <math.h>
#include <stdint.h>

// Problem constants (fixed by the dataset)
#define T_TOK 4096
#define HID   1024
#define NE    16
#define FE    512
#define FS    2048
#define NPAIR (T_TOK * 2)

// ---------------------------------------------------------------------------
// Scratch
// ---------------------------------------------------------------------------
__device__ float g_gate_s[(size_t)T_TOK * FS];   // gate, then inter (in-place)
__device__ float g_gate_r[(size_t)NPAIR * FE];   // routed gate, then inter
__device__ float g_routed[(size_t)NPAIR * HID];
__device__ int   g_cnt[NE];
__device__ int   g_bucket[NE * T_TOK];
__device__ float g_pw[NPAIR];

// ---------------------------------------------------------------------------
// Router (validated rounds 1-9)
// ---------------------------------------------------------------------------
__global__ void zero_counts_kernel() {
    if (threadIdx.x < NE) g_cnt[threadIdx.x] = 0;
}

__global__ void router_kernel(const float* __restrict__ x,
                              const float* __restrict__ rw) {
    int warp = threadIdx.x >> 5;
    int lane = threadIdx.x & 31;
    int t = blockIdx.x * (blockDim.x >> 5) + warp;
    if (t >= T_TOK) return;

    float acc[NE];
#pragma unroll
    for (int e = 0; e < NE; e++) acc[e] = 0.0f;

    const float* xr = x + (size_t)t * HID;
    for (int d = lane; d < HID; d += 32) {
        float xv = xr[d];
        const float* r = rw + (size_t)d * NE;
#pragma unroll
        for (int e = 0; e < NE; e++) acc[e] = fmaf(xv, r[e], acc[e]);
    }
#pragma unroll
    for (int e = 0; e < NE; e++) {
#pragma unroll
        for (int off = 16; off; off >>= 1)
            acc[e] += __shfl_xor_sync(0xffffffffu, acc[e], off);
    }

    if (lane == 0) {
        float mx = acc[0];
#pragma unroll
        for (int e = 1; e < NE; e++) mx = fmaxf(mx, acc[e]);
        float p[NE];
        float s = 0.0f;
#pragma unroll
        for (int e = 0; e < NE; e++) { p[e] = expf(acc[e] - mx); s += p[e]; }
        float inv = 1.0f / s;
#pragma unroll
        for (int e = 0; e < NE; e++) p[e] *= inv;

        int   i0 = 0; float w0 = p[0];
#pragma unroll
        for (int e = 1; e < NE; e++) if (p[e] > w0) { w0 = p[e]; i0 = e; }
        int   i1 = -1; float w1 = -1.0f;
#pragma unroll
        for (int e = 0; e < NE; e++)
            if (e != i0 && p[e] > w1) { w1 = p[e]; i1 = e; }

        int pos0 = atomicAdd(&g_cnt[i0], 1);
        g_bucket[i0 * T_TOK + pos0] = 2 * t;
        int pos1 = atomicAdd(&g_cnt[i1], 1);
        g_bucket[i1 * T_TOK + pos1] = 2 * t + 1;
        g_pw[2 * t]     = w0;
        g_pw[2 * t + 1] = w1;
    }
}

// ---------------------------------------------------------------------------
// fp16 hi/lo split (11-bit mantissa == tf32; same 3-MMA error bound)
// packs two adjacent-k elements into one half2 word.
// ---------------------------------------------------------------------------
__device__ __forceinline__ void split_h2(float x, float y,
                                         uint32_t& hi, uint32_t& lo) {
    half hx = __float2half_rn(x);
    half hy = __float2half_rn(y);
    half lx = __float2half_rn(x - __half2float(hx));
    half ly = __float2half_rn(y - __half2float(hy));
    __half2 h = __halves2half2(hx, hy);
    __half2 l = __halves2half2(lx, ly);
    hi = *reinterpret_cast<uint32_t*>(&h);
    lo = *reinterpret_cast<uint32_t*>(&l);
}

// mma.sync m16n8k16 fp16 -> fp32 accumulators
__device__ __forceinline__ void mma_f16(float* d,
                                        const uint32_t* a,
                                        const uint32_t* b) {
    asm volatile(
        "mma.sync.aligned.m16n8k16.row.col.f32.f16.f16.f32 "
        "{%0,%1,%2,%3}, {%4,%5,%6,%7}, {%8,%9}, {%0,%1,%2,%3};\n"
        : "+f"(d[0]), "+f"(d[1]), "+f"(d[2]), "+f"(d[3])
        : "r"(a[0]), "r"(a[1]), "r"(a[2]), "r"(a[3]),
          "r"(b[0]), "r"(b[1]));
}

// ---------------------------------------------------------------------------
// Tensor GEMM 128x128x16, 256 threads, producer-side fp16 hi/lo split,
// m16n8k16 HMMA (full-rate pipe, k=16/instr -> half the MMA+LDS of tf32 k8).
// Smem words/stage: Ah [128][12] @0 (half2: k-pairs), Al @1536,
//                   Bh [8 kpairs][136] @3072, Bl @4160; stage 5248 w.
// Bank walks: A frag g*12+t4 mod 32 all-distinct; B frag 8*t4+g all-distinct.
// MODE 0: plain. MODE 1: gather x rows by pair>>1, scatter C by pair.
// MODE 2: gather rows by pair, scale C by router weight, scatter by pair.
// FUSE 1: C[..] = silu(G[..]) * acc.
// ---------------------------------------------------------------------------
#define BM 128
#define BN 128
#define BK 16
#define A_PAD 12
#define B_PAD 136
#define OFF_AL 1536
#define OFF_BH 3072
#define OFF_BL 4160
#define STAGEF 5248
#define SMEM_DYN (2 * STAGEF * 4)

template <int MODE, int FUSE>
__global__ __launch_bounds__(256, 2)
void tgemm_kernel(const float* __restrict__ A,
                  const float* __restrict__ B,
                  float* __restrict__ C,
                  const float* __restrict__ G,
                  int M, int N, int K) {
    int e = blockIdx.z;
    int m_rows = M;
    const int* rowlist = nullptr;
    if (MODE != 0) {
        m_rows  = g_cnt[e];
        rowlist = g_bucket + e * T_TOK;
        B += (size_t)e * K * N;
    }
    const int m0 = blockIdx.y * BM;
    const int n0 = blockIdx.x * BN;
    if (m0 >= m_rows) return;

    extern __shared__ uint32_t sm[];

    const int tid  = threadIdx.x;
    const int lane = tid & 31;
    const int wid  = tid >> 5;
    const int warp_m = wid >> 2;          // 0..1
    const int warp_n = wid & 3;           // 0..3
    const int g  = lane >> 2;             // 0..7
    const int t4 = lane & 3;              // 0..3
    const int mb = warp_m * 64;
    const int nb = warp_n * 32;

    // --- loader mappings ---
    // A: m = tid>>1 (0..127), k-octet = (tid&1)*8 -> word quad (tid&1)*4
    const int am  = tid >> 1;
    const int akq = (tid & 1) * 8;
    const int aw  = (tid & 1) * 4;
    // B: kpair p = tid>>5 (0..7) -> gmem rows 2p, 2p+1; cols (tid&31)*4
    const int bp  = tid >> 5;
    const int bc4 = (tid & 31) * 4;

    const int  ar_g = m0 + am;
    const bool av   = ar_g < m_rows;
    const int  aidx = av ? ar_g : 0;
    const float* Arow;
    if (MODE == 0)      Arow = A + (size_t)aidx * K;
    else if (MODE == 1) Arow = A + (size_t)(rowlist[aidx] >> 1) * K;
    else                Arow = A + (size_t)rowlist[aidx] * K;

    const float* Bp0 = B + (size_t)(2 * bp) * N + n0 + bc4;      // row 2p
    const float* Bp1 = B + (size_t)(2 * bp + 1) * N + n0 + bc4;  // row 2p+1

    auto stage_store = [&](int s, const float* va, const float4 vb0,
                           const float4 vb1) {
        uint32_t* st = sm + s * STAGEF;
        // A: 8 consecutive k -> 4 half2 hi words + 4 lo words
        uint32_t h[4], l[4];
#pragma unroll
        for (int j = 0; j < 4; j++)
            split_h2(va[2 * j], va[2 * j + 1], h[j], l[j]);
        *(uint4*)(st + am * A_PAD + aw)          = make_uint4(h[0], h[1], h[2], h[3]);
        *(uint4*)(st + OFF_AL + am * A_PAD + aw) = make_uint4(l[0], l[1], l[2], l[3]);
        // B: 4 cols, pack (k=2p, k=2p+1) per word
        const float bx[4] = {vb0.x, vb0.y, vb0.z, vb0.w};
        const float by[4] = {vb1.x, vb1.y, vb1.z, vb1.w};
#pragma unroll
        for (int i = 0; i < 4; i++)
            split_h2(bx[i], by[i], h[i], l[i]);
        *(uint4*)(st + OFF_BH + bp * B_PAD + bc4) = make_uint4(h[0], h[1], h[2], h[3]);
        *(uint4*)(st + OFF_BL + bp * B_PAD + bc4) = make_uint4(l[0], l[1], l[2], l[3]);
    };

    // Prefetch stage 0
    float va[8];
    float4 vb0, vb1;
    {
#pragma unroll
        for (int i = 0; i < 8; i++) va[i] = av ? Arow[akq + i] : 0.0f;
        vb0 = *(const float4*)Bp0;
        vb1 = *(const float4*)Bp1;
        stage_store(0, va, vb0, vb1);
    }
    __syncthreads();

    float acc[4][4][4];
#pragma unroll
    for (int i = 0; i < 4; i++)
#pragma unroll
        for (int j = 0; j < 4; j++)
#pragma unroll
            for (int r = 0; r < 4; r++) acc[i][j][r] = 0.0f;

    const int KT = K / BK;

    for (int kt = 0; kt < KT; kt++) {
        const int cur = kt & 1;
        if (kt + 1 < KT) {
            const int k0 = (kt + 1) * BK;
#pragma unroll
            for (int i = 0; i < 8; i++) va[i] = av ? Arow[k0 + akq + i] : 0.0f;
            vb0 = *(const float4*)(Bp0 + (size_t)k0 * N);
            vb1 = *(const float4*)(Bp1 + (size_t)k0 * N);
        }

        const uint32_t* Ah = sm + cur * STAGEF;
        const uint32_t* Al = Ah + OFF_AL;
        const uint32_t* Bh = sm + cur * STAGEF + OFF_BH;
        const uint32_t* Bl = Bh + (OFF_BL - OFF_BH);

        // one m16n8k16 group covers the whole BK=16 tile
        uint32_t bh[4][2], bl[4][2];
#pragma unroll
        for (int nt = 0; nt < 4; nt++) {
            const int col = nb + nt * 8 + g;
            bh[nt][0] = Bh[t4 * B_PAD + col];
            bh[nt][1] = Bh[(t4 + 4) * B_PAD + col];
            bl[nt][0] = Bl[t4 * B_PAD + col];
            bl[nt][1] = Bl[(t4 + 4) * B_PAD + col];
        }
#pragma unroll
        for (int mt = 0; mt < 4; mt++) {
            const int r0 = (mb + mt * 16 + g) * A_PAD;
            const int r1 = r0 + 8 * A_PAD;
            uint32_t ah[4], al[4];
            ah[0] = Ah[r0 + t4];
            ah[1] = Ah[r1 + t4];
            ah[2] = Ah[r0 + t4 + 4];
            ah[3] = Ah[r1 + t4 + 4];
            al[0] = Al[r0 + t4];
            al[1] = Al[r1 + t4];
            al[2] = Al[r0 + t4 + 4];
            al[3] = Al[r1 + t4 + 4];
            // per-acc term order hh -> hl -> lh (matches validated rounds)
#pragma unroll
            for (int nt = 0; nt < 4; nt++) mma_f16(acc[mt][nt], ah, bh[nt]);
#pragma unroll
            for (int nt = 0; nt < 4; nt++) mma_f16(acc[mt][nt], ah, bl[nt]);
#pragma unroll
            for (int nt = 0; nt < 4; nt++) mma_f16(acc[mt][nt], al, bh[nt]);
        }

        if (kt + 1 < KT) stage_store(cur ^ 1, va, vb0, vb1);
        __syncthreads();
    }

    // Epilogue (+ optional silu(G)*acc fusion) — unchanged from R7/R9
#pragma unroll
    for (int mt = 0; mt < 4; mt++) {
        const int r0 = m0 + mb + mt * 16 + g;
        const int r1 = r0 + 8;
        float* Crow0 = nullptr; float* Crow1 = nullptr;
        const float* Grow0 = nullptr; const float* Grow1 = nullptr;
        float s0 = 1.0f, s1 = 1.0f;
        if (r0 < m_rows) {
            size_t ro;
            if (MODE == 0) ro = (size_t)r0 * N;
            else {
                const int p = rowlist[r0];
                ro = (size_t)p * N;
                if (MODE == 2) s0 = g_pw[p];
            }
            Crow0 = C + ro;
            if (FUSE) Grow0 = G + ro;
        }
        if (r1 < m_rows) {
            size_t ro;
            if (MODE == 0) ro = (size_t)r1 * N;
            else {
                const int p = rowlist[r1];
                ro = (size_t)p * N;
                if (MODE == 2) s1 = g_pw[p];
            }
            Crow1 = C + ro;
            if (FUSE) Grow1 = G + ro;
        }
#pragma unroll
        for (int nt = 0; nt < 4; nt++) {
            const int c = n0 + nb + nt * 8 + 2 * t4;
            if (Crow0) {
                float o0 = acc[mt][nt][0] * s0, o1 = acc[mt][nt][1] * s0;
                if (FUSE) {
                    float2 gv = *(const float2*)(Grow0 + c);
                    o0 *= gv.x / (1.0f + expf(-gv.x));
                    o1 *= gv.y / (1.0f + expf(-gv.y));
                }
                *(float2*)(Crow0 + c) = make_float2(o0, o1);
            }
            if (Crow1) {
                float o0 = acc[mt][nt][2] * s1, o1 = acc[mt][nt][3] * s1;
                if (FUSE) {
                    float2 gv = *(const float2*)(Grow1 + c);
                    o0 *= gv.x / (1.0f + expf(-gv.x));
                    o1 *= gv.y / (1.0f + expf(-gv.y));
                }
                *(float2*)(Crow1 + c) = make_float2(o0, o1);
            }
        }
    }
}

// ---------------------------------------------------------------------------
// Final: out[t] += routed[2t] + routed[2t+1]
// ---------------------------------------------------------------------------
__global__ void final_add_kernel(float* __restrict__ out) {
    int i = blockIdx.x * blockDim.x + threadIdx.x;
    if (i >= T_TOK * HID / 4) return;
    const int t  = i >> 8;
    const int d4 = i & 255;
    float4 o = ((const float4*)out)[i];
    float4 a = ((const float4*)(g_routed + (size_t)(2 * t) * HID))[d4];
    float4 b = ((const float4*)(g_routed + (size_t)(2 * t + 1) * HID))[d4];
    o.x += a.x + b.x;
    o.y += a.y + b.y;
    o.z += a.z + b.z;
    o.w += a.w + b.w;
    ((float4*)out)[i] = o;
}

// ---------------------------------------------------------------------------
// Launch
// ---------------------------------------------------------------------------
extern "C" void kernel_launch(void* const* d_in, const int* in_sizes, int n_in,
                              void* d_out, int out_size) {
    const float* x  = (const float*)d_in[0];
    const float* rw = (const float*)d_in[1];
    const float* eg = (const float*)d_in[2];
    const float* eu = (const float*)d_in[3];
    const float* ed = (const float*)d_in[4];
    const float* sg = (const float*)d_in[5];
    const float* su = (const float*)d_in[6];
    const float* sd = (const float*)d_in[7];
    float* out = (float*)d_out;

    void *p_gate_s, *p_gate_r, *p_routed;
    cudaGetSymbolAddress(&p_gate_s, g_gate_s);
    cudaGetSymbolAddress(&p_gate_r, g_gate_r);
    cudaGetSymbolAddress(&p_routed, g_routed);

    cudaFuncSetAttribute(tgemm_kernel<0, 0>,
                         cudaFuncAttributeMaxDynamicSharedMemorySize, SMEM_DYN);
    cudaFuncSetAttribute(tgemm_kernel<0, 1>,
                         cudaFuncAttributeMaxDynamicSharedMemorySize, SMEM_DYN);
    cudaFuncSetAttribute(tgemm_kernel<1, 0>,
                         cudaFuncAttributeMaxDynamicSharedMemorySize, SMEM_DYN);
    cudaFuncSetAttribute(tgemm_kernel<1, 1>,
                         cudaFuncAttributeMaxDynamicSharedMemorySize, SMEM_DYN);
    cudaFuncSetAttribute(tgemm_kernel<2, 0>,
                         cudaFuncAttributeMaxDynamicSharedMemorySize, SMEM_DYN);

    zero_counts_kernel<<<1, 32>>>();
    router_kernel<<<T_TOK / 4, 128>>>(x, rw);

    // Shared expert: gate -> (up, silu fused) -> down
    tgemm_kernel<0, 0><<<dim3(FS / BN, T_TOK / BM, 1), 256, SMEM_DYN>>>(
        x, sg, (float*)p_gate_s, nullptr, T_TOK, FS, HID);
    tgemm_kernel<0, 1><<<dim3(FS / BN, T_TOK / BM, 1), 256, SMEM_DYN>>>(
        x, su, (float*)p_gate_s, (const float*)p_gate_s, T_TOK, FS, HID);
    tgemm_kernel<0, 0><<<dim3(HID / BN, T_TOK / BM, 1), 256, SMEM_DYN>>>(
        (const float*)p_gate_s, sd, out, nullptr, T_TOK, HID, FS);

    // Routed experts: gate -> (up, silu fused) -> down (scaled scatter)
    tgemm_kernel<1, 0><<<dim3(FE / BN, T_TOK / BM, NE), 256, SMEM_DYN>>>(
        x, eg, (float*)p_gate_r, nullptr, 0, FE, HID);
    tgemm_kernel<1, 1><<<dim3(FE / BN, T_TOK / BM, NE), 256, SMEM_DYN>>>(
        x, eu, (float*)p_gate_r, (const float*)p_gate_r, 0, FE, HID);
    tgemm_kernel<2, 0><<<dim3(HID / BN, T_TOK / BM, NE), 256, SMEM_DYN>>>(
        (const float*)p_gate_r, ed, (float*)p_routed, nullptr, 0, HID, FE);

    final_add_kernel<<<(T_TOK * HID / 4) / 256, 256>>>(out);
}

// round 11
// speedup vs baseline: 1.7569x; 1.2603x over previous
#include <cuda_runtime.h>
#include <cuda_fp16.h>
#include <math.h>
#include <stdint.h>

// Problem constants (fixed by the dataset)
#define T_TOK 4096
#define HID   1024
#define NE    16
#define FE    512
#define FS    2048
#define NPAIR (T_TOK * 2)

// ---------------------------------------------------------------------------
// Scratch (all half2-packed words are uint32)
// ---------------------------------------------------------------------------
__device__ float    g_gate_s[(size_t)T_TOK * FS];
__device__ float    g_gate_r[(size_t)NPAIR * FE];
__device__ float    g_routed[(size_t)NPAIR * HID];
__device__ int      g_cnt[NE];
__device__ int      g_bucket[NE * T_TOK];
__device__ float    g_pw[NPAIR];
// pre-split inputs (hi/lo fp16, half2-packed along K)
__device__ uint32_t g_xh[(size_t)T_TOK * HID / 2];
__device__ uint32_t g_xl[(size_t)T_TOK * HID / 2];
__device__ uint32_t g_sgh[(size_t)HID / 2 * FS],  g_sgl[(size_t)HID / 2 * FS];
__device__ uint32_t g_suh[(size_t)HID / 2 * FS],  g_sul[(size_t)HID / 2 * FS];
__device__ uint32_t g_sdh[(size_t)FS / 2 * HID],  g_sdl[(size_t)FS / 2 * HID];
__device__ uint32_t g_egh[(size_t)NE * HID / 2 * FE], g_egl[(size_t)NE * HID / 2 * FE];
__device__ uint32_t g_euh[(size_t)NE * HID / 2 * FE], g_eul[(size_t)NE * HID / 2 * FE];
__device__ uint32_t g_edh[(size_t)NE * FE / 2 * HID], g_edl[(size_t)NE * FE / 2 * HID];
// pre-split intermediates (written by FUSE epilogues)
__device__ uint32_t g_ish[(size_t)T_TOK * FS / 2],  g_isl[(size_t)T_TOK * FS / 2];
__device__ uint32_t g_irh[(size_t)NPAIR * FE / 2],  g_irl[(size_t)NPAIR * FE / 2];

// ---------------------------------------------------------------------------
// fp16 hi/lo split (11-bit mantissa == tf32; validated R10)
// ---------------------------------------------------------------------------
__device__ __forceinline__ void split_h2(float x, float y,
                                         uint32_t& hi, uint32_t& lo) {
    half hx = __float2half_rn(x);
    half hy = __float2half_rn(y);
    half lx = __float2half_rn(x - __half2float(hx));
    half ly = __float2half_rn(y - __half2float(hy));
    __half2 h = __halves2half2(hx, hy);
    __half2 l = __halves2half2(lx, ly);
    hi = *reinterpret_cast<uint32_t*>(&h);
    lo = *reinterpret_cast<uint32_t*>(&l);
}

__device__ __forceinline__ void mma_f16(float* d,
                                        const uint32_t* a,
                                        const uint32_t* b) {
    asm volatile(
        "mma.sync.aligned.m16n8k16.row.col.f32.f16.f16.f32 "
        "{%0,%1,%2,%3}, {%4,%5,%6,%7}, {%8,%9}, {%0,%1,%2,%3};\n"
        : "+f"(d[0]), "+f"(d[1]), "+f"(d[2]), "+f"(d[3])
        : "r"(a[0]), "r"(a[1]), "r"(a[2]), "r"(a[3]),
          "r"(b[0]), "r"(b[1]));
}

__device__ __forceinline__ void cp_async16(uint32_t dst, const void* src,
                                           int src_bytes) {
    asm volatile("cp.async.cg.shared.global [%0], [%1], 16, %2;\n"
                 :: "r"(dst), "l"(src), "r"(src_bytes) : "memory");
}
#define CP_COMMIT() asm volatile("cp.async.commit_group;" ::: "memory")
#define CP_WAIT1()  asm volatile("cp.async.wait_group 1;" ::: "memory")

__device__ __forceinline__ uint32_t cvta_smem(const void* p) {
    uint32_t a;
    asm("{ .reg .u64 t; cvta.to.shared.u64 t, %1; cvt.u32.u64 %0, t; }"
        : "=r"(a) : "l"(p));
    return a;
}

// ---------------------------------------------------------------------------
// Splitters (run once per launch)
// ---------------------------------------------------------------------------
// A-type: pairs along contiguous dim -> word i = half2(src[2i], src[2i+1])
__global__ void split_contig_kernel(const float* __restrict__ src,
                                    uint32_t* __restrict__ hi,
                                    uint32_t* __restrict__ lo, int nwords) {
    int i = blockIdx.x * 256 + threadIdx.x;
    if (i >= nwords) return;
    float2 v = ((const float2*)src)[i];
    uint32_t h, l;
    split_h2(v.x, v.y, h, l);
    hi[i] = h; lo[i] = l;
}
// B-type: pairs along K (row stride N): word(kp,n) = half2(src[2kp][n], src[2kp+1][n])
__global__ void split_strided_kernel(const float* __restrict__ src,
                                     uint32_t* __restrict__ hi,
                                     uint32_t* __restrict__ lo,
                                     int nwords, int N) {
    int i = blockIdx.x * 256 + threadIdx.x;
    if (i >= nwords) return;
    int kp = i / N, n = i - kp * N;
    float a = src[(size_t)(2 * kp) * N + n];
    float b = src[(size_t)(2 * kp + 1) * N + n];
    uint32_t h, l;
    split_h2(a, b, h, l);
    hi[i] = h; lo[i] = l;
}

// ---------------------------------------------------------------------------
// Router (validated rounds 1-10)
// ---------------------------------------------------------------------------
__global__ void zero_counts_kernel() {
    if (threadIdx.x < NE) g_cnt[threadIdx.x] = 0;
}

__global__ void router_kernel(const float* __restrict__ x,
                              const float* __restrict__ rw) {
    int warp = threadIdx.x >> 5;
    int lane = threadIdx.x & 31;
    int t = blockIdx.x * (blockDim.x >> 5) + warp;
    if (t >= T_TOK) return;

    float acc[NE];
#pragma unroll
    for (int e = 0; e < NE; e++) acc[e] = 0.0f;

    const float* xr = x + (size_t)t * HID;
    for (int d = lane; d < HID; d += 32) {
        float xv = xr[d];
        const float* r = rw + (size_t)d * NE;
#pragma unroll
        for (int e = 0; e < NE; e++) acc[e] = fmaf(xv, r[e], acc[e]);
    }
#pragma unroll
    for (int e = 0; e < NE; e++) {
#pragma unroll
        for (int off = 16; off; off >>= 1)
            acc[e] += __shfl_xor_sync(0xffffffffu, acc[e], off);
    }

    if (lane == 0) {
        float mx = acc[0];
#pragma unroll
        for (int e = 1; e < NE; e++) mx = fmaxf(mx, acc[e]);
        float p[NE];
        float s = 0.0f;
#pragma unroll
        for (int e = 0; e < NE; e++) { p[e] = expf(acc[e] - mx); s += p[e]; }
        float inv = 1.0f / s;
#pragma unroll
        for (int e = 0; e < NE; e++) p[e] *= inv;

        int   i0 = 0; float w0 = p[0];
#pragma unroll
        for (int e = 1; e < NE; e++) if (p[e] > w0) { w0 = p[e]; i0 = e; }
        int   i1 = -1; float w1 = -1.0f;
#pragma unroll
        for (int e = 0; e < NE; e++)
            if (e != i0 && p[e] > w1) { w1 = p[e]; i1 = e; }

        int pos0 = atomicAdd(&g_cnt[i0], 1);
        g_bucket[i0 * T_TOK + pos0] = 2 * t;
        int pos1 = atomicAdd(&g_cnt[i1], 1);
        g_bucket[i1 * T_TOK + pos1] = 2 * t + 1;
        g_pw[2 * t]     = w0;
        g_pw[2 * t + 1] = w1;
    }
}

// ---------------------------------------------------------------------------
// Tensor GEMM 128x128x16, 256 threads, pre-split fp16 inputs, cp.async
// 3-stage pipeline, m16n8k16 HMMA (fragment maps validated R10).
// A gmem: [rows][K/2] half2 words.  B gmem: [K/2][N] half2 words.
// Smem words/stage: Ah [128][12] @0, Al @1536, Bh [8][136] @3072, Bl @4160.
// MODE 0: plain. MODE 1: gather x rows by pair>>1, scatter C by pair.
// MODE 2: gather rows by pair, scale C by router weight, scatter by pair.
// FUSE 1: write CH/CL = split(silu(G) * acc) instead of C.
// ---------------------------------------------------------------------------
#define BM 128
#define BN 128
#define BK 16
#define A_PAD 12
#define B_PAD 136
#define OFF_AL 1536
#define OFF_BH 3072
#define OFF_BL 4160
#define STAGEF 5248
#define NSTG 3
#define SMEM_DYN (NSTG * STAGEF * 4)

template <int MODE, int FUSE>
__global__ __launch_bounds__(256, 2)
void tgemm_kernel(const uint32_t* __restrict__ Ahg,
                  const uint32_t* __restrict__ Alg,
                  const uint32_t* __restrict__ Bhg,
                  const uint32_t* __restrict__ Blg,
                  float* __restrict__ C,
                  uint32_t* __restrict__ CH,
                  uint32_t* __restrict__ CL,
                  const float* __restrict__ G,
                  int M, int N, int K) {
    const int e = blockIdx.z;
    int m_rows = M;
    const int* rowlist = nullptr;
    if (MODE != 0) {
        m_rows  = g_cnt[e];
        rowlist = g_bucket + e * T_TOK;
        Bhg += (size_t)e * (K / 2) * N;
        Blg += (size_t)e * (K / 2) * N;
    }
    const int m0 = blockIdx.y * BM;
    const int n0 = blockIdx.x * BN;
    if (m0 >= m_rows) return;

    extern __shared__ uint32_t sm[];
    const uint32_t smem_base = cvta_smem(sm);

    const int tid  = threadIdx.x;
    const int lane = tid & 31;
    const int wid  = tid >> 5;
    const int warp_m = wid >> 2;
    const int warp_n = wid & 3;
    const int g  = lane >> 2;
    const int t4 = lane & 3;
    const int mb = warp_m * 64;
    const int nb = warp_n * 32;

    const int KW = K / 2;  // words per A row

    // --- cp.async loader mappings ---
    const int am     = tid >> 1;
    const int achunk = (tid & 1) * 4;          // word offset within 8-word row seg
    const int bkp    = tid >> 5;               // 0..7 kpair
    const int bc4    = (tid & 31) * 4;         // col word quad

    const int  ar_g = m0 + am;
    const bool av   = ar_g < m_rows;
    const int  aidx = av ? ar_g : 0;
    int rowidx;
    if (MODE == 0)      rowidx = aidx;
    else if (MODE == 1) rowidx = rowlist[aidx] >> 1;
    else                rowidx = rowlist[aidx];
    const uint32_t* ArH = Ahg + (size_t)rowidx * KW + achunk;
    const uint32_t* ArL = Alg + (size_t)rowidx * KW + achunk;
    const uint32_t* BgH = Bhg + (size_t)bkp * N + n0 + bc4;
    const uint32_t* BgL = Blg + (size_t)bkp * N + n0 + bc4;
    const int abytes = av ? 16 : 0;

    const uint32_t a_dst  = smem_base + (am * A_PAD + achunk) * 4;
    const uint32_t b_dst  = smem_base + (bkp * B_PAD + bc4) * 4;
    const int KT = K / BK;

    auto issue_stage = [&](int kt) {
        const uint32_t so = (uint32_t)((kt % NSTG) * (STAGEF * 4));
        const int kw0 = kt * 8;
        cp_async16(a_dst + so,              ArH + kw0, abytes);
        cp_async16(a_dst + so + OFF_AL * 4, ArL + kw0, abytes);
        cp_async16(b_dst + so + OFF_BH * 4, BgH + (size_t)kw0 * N, 16);
        cp_async16(b_dst + so + OFF_BL * 4, BgL + (size_t)kw0 * N, 16);
    };

    // Prologue: stages 0, 1
    issue_stage(0); CP_COMMIT();
    issue_stage(1); CP_COMMIT();

    float acc[4][4][4];
#pragma unroll
    for (int i = 0; i < 4; i++)
#pragma unroll
        for (int j = 0; j < 4; j++)
#pragma unroll
            for (int r = 0; r < 4; r++) acc[i][j][r] = 0.0f;

    for (int kt = 0; kt < KT; kt++) {
        CP_WAIT1();
        __syncthreads();
        if (kt + 2 < KT) issue_stage(kt + 2);
        CP_COMMIT();

        const uint32_t* Ah = sm + (kt % NSTG) * STAGEF;
        const uint32_t* Al = Ah + OFF_AL;
        const uint32_t* Bh = sm + (kt % NSTG) * STAGEF + OFF_BH;
        const uint32_t* Bl = Bh + (OFF_BL - OFF_BH);

        uint32_t bh[4][2], bl[4][2];
#pragma unroll
        for (int nt = 0; nt < 4; nt++) {
            const int col = nb + nt * 8 + g;
            bh[nt][0] = Bh[t4 * B_PAD + col];
            bh[nt][1] = Bh[(t4 + 4) * B_PAD + col];
            bl[nt][0] = Bl[t4 * B_PAD + col];
            bl[nt][1] = Bl[(t4 + 4) * B_PAD + col];
        }
#pragma unroll
        for (int mt = 0; mt < 4; mt++) {
            const int r0 = (mb + mt * 16 + g) * A_PAD;
            const int r1 = r0 + 8 * A_PAD;
            uint32_t ah[4], al[4];
            ah[0] = Ah[r0 + t4];
            ah[1] = Ah[r1 + t4];
            ah[2] = Ah[r0 + t4 + 4];
            ah[3] = Ah[r1 + t4 + 4];
            al[0] = Al[r0 + t4];
            al[1] = Al[r1 + t4];
            al[2] = Al[r0 + t4 + 4];
            al[3] = Al[r1 + t4 + 4];
#pragma unroll
            for (int nt = 0; nt < 4; nt++) mma_f16(acc[mt][nt], ah, bh[nt]);
#pragma unroll
            for (int nt = 0; nt < 4; nt++) mma_f16(acc[mt][nt], ah, bl[nt]);
#pragma unroll
            for (int nt = 0; nt < 4; nt++) mma_f16(acc[mt][nt], al, bh[nt]);
        }
    }

    // Epilogue
#pragma unroll
    for (int mt = 0; mt < 4; mt++) {
        const int r0 = m0 + mb + mt * 16 + g;
        const int r1 = r0 + 8;
        size_t ro0 = 0, ro1 = 0;
        bool v0 = r0 < m_rows, v1 = r1 < m_rows;
        float s0 = 1.0f, s1 = 1.0f;
        if (v0) {
            if (MODE == 0) ro0 = (size_t)r0 * N;
            else {
                const int p = rowlist[r0];
                ro0 = (size_t)p * N;
                if (MODE == 2) s0 = g_pw[p];
            }
        }
        if (v1) {
            if (MODE == 0) ro1 = (size_t)r1 * N;
            else {
                const int p = rowlist[r1];
                ro1 = (size_t)p * N;
                if (MODE == 2) s1 = g_pw[p];
            }
        }
#pragma unroll
        for (int nt = 0; nt < 4; nt++) {
            const int c = n0 + nb + nt * 8 + 2 * t4;
            if (v0) {
                float o0 = acc[mt][nt][0] * s0, o1 = acc[mt][nt][1] * s0;
                if (FUSE) {
                    float2 gv = *(const float2*)(G + ro0 + c);
                    o0 *= gv.x / (1.0f + expf(-gv.x));
                    o1 *= gv.y / (1.0f + expf(-gv.y));
                    uint32_t h, l;
                    split_h2(o0, o1, h, l);
                    const size_t wi = (ro0 + c) >> 1;
                    CH[wi] = h; CL[wi] = l;
                } else {
                    *(float2*)(C + ro0 + c) = make_float2(o0, o1);
                }
            }
            if (v1) {
                float o0 = acc[mt][nt][2] * s1, o1 = acc[mt][nt][3] * s1;
                if (FUSE) {
                    float2 gv = *(const float2*)(G + ro1 + c);
                    o0 *= gv.x / (1.0f + expf(-gv.x));
                    o1 *= gv.y / (1.0f + expf(-gv.y));
                    uint32_t h, l;
                    split_h2(o0, o1, h, l);
                    const size_t wi = (ro1 + c) >> 1;
                    CH[wi] = h; CL[wi] = l;
                } else {
                    *(float2*)(C + ro1 + c) = make_float2(o0, o1);
                }
            }
        }
    }
}

// ---------------------------------------------------------------------------
// Final: out[t] += routed[2t] + routed[2t+1]
// ---------------------------------------------------------------------------
__global__ void final_add_kernel(float* __restrict__ out) {
    int i = blockIdx.x * blockDim.x + threadIdx.x;
    if (i >= T_TOK * HID / 4) return;
    const int t  = i >> 8;
    const int d4 = i & 255;
    float4 o = ((const float4*)out)[i];
    float4 a = ((const float4*)(g_routed + (size_t)(2 * t) * HID))[d4];
    float4 b = ((const float4*)(g_routed + (size_t)(2 * t + 1) * HID))[d4];
    o.x += a.x + b.x;
    o.y += a.y + b.y;
    o.z += a.z + b.z;
    o.w += a.w + b.w;
    ((float4*)out)[i] = o;
}

// ---------------------------------------------------------------------------
// Launch
// ---------------------------------------------------------------------------
extern "C" void kernel_launch(void* const* d_in, const int* in_sizes, int n_in,
                              void* d_out, int out_size) {
    const float* x  = (const float*)d_in[0];
    const float* rw = (const float*)d_in[1];
    const float* eg = (const float*)d_in[2];
    const float* eu = (const float*)d_in[3];
    const float* ed = (const float*)d_in[4];
    const float* sg = (const float*)d_in[5];
    const float* su = (const float*)d_in[6];
    const float* sd = (const float*)d_in[7];
    float* out = (float*)d_out;

#define SYM(p, s) void* p; cudaGetSymbolAddress(&p, s)
    SYM(p_gate_s, g_gate_s); SYM(p_gate_r, g_gate_r); SYM(p_routed, g_routed);
    SYM(p_xh, g_xh);   SYM(p_xl, g_xl);
    SYM(p_sgh, g_sgh); SYM(p_sgl, g_sgl);
    SYM(p_suh, g_suh); SYM(p_sul, g_sul);
    SYM(p_sdh, g_sdh); SYM(p_sdl, g_sdl);
    SYM(p_egh, g_egh); SYM(p_egl, g_egl);
    SYM(p_euh, g_euh); SYM(p_eul, g_eul);
    SYM(p_edh, g_edh); SYM(p_edl, g_edl);
    SYM(p_ish, g_ish); SYM(p_isl, g_isl);
    SYM(p_irh, g_irh); SYM(p_irl, g_irl);
#undef SYM

    cudaFuncSetAttribute(tgemm_kernel<0, 0>,
                         cudaFuncAttributeMaxDynamicSharedMemorySize, SMEM_DYN);
    cudaFuncSetAttribute(tgemm_kernel<0, 1>,
                         cudaFuncAttributeMaxDynamicSharedMemorySize, SMEM_DYN);
    cudaFuncSetAttribute(tgemm_kernel<1, 0>,
                         cudaFuncAttributeMaxDynamicSharedMemorySize, SMEM_DYN);
    cudaFuncSetAttribute(tgemm_kernel<1, 1>,
                         cudaFuncAttributeMaxDynamicSharedMemorySize, SMEM_DYN);
    cudaFuncSetAttribute(tgemm_kernel<2, 0>,
                         cudaFuncAttributeMaxDynamicSharedMemorySize, SMEM_DYN);

    zero_counts_kernel<<<1, 32>>>();
    router_kernel<<<T_TOK / 4, 128>>>(x, rw);

    // Pre-split inputs (once per launch; deterministic)
    split_contig_kernel<<<(T_TOK * HID / 2) / 256, 256>>>(
        x, (uint32_t*)p_xh, (uint32_t*)p_xl, T_TOK * HID / 2);
    split_strided_kernel<<<(HID / 2 * FS) / 256, 256>>>(
        sg, (uint32_t*)p_sgh, (uint32_t*)p_sgl, HID / 2 * FS, FS);
    split_strided_kernel<<<(HID / 2 * FS) / 256, 256>>>(
        su, (uint32_t*)p_suh, (uint32_t*)p_sul, HID / 2 * FS, FS);
    split_strided_kernel<<<(FS / 2 * HID) / 256, 256>>>(
        sd, (uint32_t*)p_sdh, (uint32_t*)p_sdl, FS / 2 * HID, HID);
    split_strided_kernel<<<(NE * HID / 2 * FE) / 256, 256>>>(
        eg, (uint32_t*)p_egh, (uint32_t*)p_egl, NE * HID / 2 * FE, FE);
    split_strided_kernel<<<(NE * HID / 2 * FE) / 256, 256>>>(
        eu, (uint32_t*)p_euh, (uint32_t*)p_eul, NE * HID / 2 * FE, FE);
    split_strided_kernel<<<(NE * FE / 2 * HID) / 256, 256>>>(
        ed, (uint32_t*)p_edh, (uint32_t*)p_edl, NE * FE / 2 * HID, HID);
    // note: expert pair-rows never cross expert boundaries (FE, HID even)

    // Shared expert: gate -> (up, silu fused, split-write) -> down
    tgemm_kernel<0, 0><<<dim3(FS / BN, T_TOK / BM, 1), 256, SMEM_DYN>>>(
        (const uint32_t*)p_xh, (const uint32_t*)p_xl,
        (const uint32_t*)p_sgh, (const uint32_t*)p_sgl,
        (float*)p_gate_s, nullptr, nullptr, nullptr, T_TOK, FS, HID);
    tgemm_kernel<0, 1><<<dim3(FS / BN, T_TOK / BM, 1), 256, SMEM_DYN>>>(
        (const uint32_t*)p_xh, (const uint32_t*)p_xl,
        (const uint32_t*)p_suh, (const uint32_t*)p_sul,
        nullptr, (uint32_t*)p_ish, (uint32_t*)p_isl,
        (const float*)p_gate_s, T_TOK, FS, HID);
    tgemm_kernel<0, 0><<<dim3(HID / BN, T_TOK / BM, 1), 256, SMEM_DYN>>>(
        (const uint32_t*)p_ish, (const uint32_t*)p_isl,
        (const uint32_t*)p_sdh, (const uint32_t*)p_sdl,
        out, nullptr, nullptr, nullptr, T_TOK, HID, FS);

    // Routed experts
    tgemm_kernel<1, 0><<<dim3(FE / BN, T_TOK / BM, NE), 256, SMEM_DYN>>>(
        (const uint32_t*)p_xh, (const uint32_t*)p_xl,
        (const uint32_t*)p_egh, (const uint32_t*)p_egl,
        (float*)p_gate_r, nullptr, nullptr, nullptr, 0, FE, HID);
    tgemm_kernel<1, 1><<<dim3(FE / BN, T_TOK / BM, NE), 256, SMEM_DYN>>>(
        (const uint32_t*)p_xh, (const uint32_t*)p_xl,
        (const uint32_t*)p_euh, (const uint32_t*)p_eul,
        nullptr, (uint32_t*)p_irh, (uint32_t*)p_irl,
        (const float*)p_gate_r, 0, FE, HID);
    tgemm_kernel<2, 0><<<dim3(HID / BN, T_TOK / BM, NE), 256, SMEM_DYN>>>(
        (const uint32_t*)p_irh, (const uint32_t*)p_irl,
        (const uint32_t*)p_edh, (const uint32_t*)p_edl,
        (float*)p_routed, nullptr, nullptr, nullptr, 0, HID, FE);

    final_add_kernel<<<(T_TOK * HID / 4) / 256, 256>>>(out);
}

// round 12
// speedup vs baseline: 1.8129x; 1.0318x over previous
#include <cuda_runtime.h>
#include <cuda_fp16.h>
#include <math.h>
#include <stdint.h>

// Problem constants (fixed by the dataset)
#define T_TOK 4096
#define HID   1024
#define NE    16
#define FE    512
#define FS    2048
#define NPAIR (T_TOK * 2)

// ---------------------------------------------------------------------------
// Scratch (all half2-packed words are uint32)
// ---------------------------------------------------------------------------
__device__ float    g_gate_s[(size_t)T_TOK * FS];
__device__ float    g_gate_r[(size_t)NPAIR * FE];
__device__ int      g_cnt[NE];
__device__ int      g_bucket[NE * T_TOK];
__device__ float    g_pw[NPAIR];
// pre-split inputs (hi/lo fp16, half2-packed along K)
__device__ uint32_t g_xh[(size_t)T_TOK * HID / 2];
__device__ uint32_t g_xl[(size_t)T_TOK * HID / 2];
__device__ uint32_t g_sgh[(size_t)HID / 2 * FS],  g_sgl[(size_t)HID / 2 * FS];
__device__ uint32_t g_suh[(size_t)HID / 2 * FS],  g_sul[(size_t)HID / 2 * FS];
__device__ uint32_t g_sdh[(size_t)FS / 2 * HID],  g_sdl[(size_t)FS / 2 * HID];
__device__ uint32_t g_egh[(size_t)NE * HID / 2 * FE], g_egl[(size_t)NE * HID / 2 * FE];
__device__ uint32_t g_euh[(size_t)NE * HID / 2 * FE], g_eul[(size_t)NE * HID / 2 * FE];
__device__ uint32_t g_edh[(size_t)NE * FE / 2 * HID], g_edl[(size_t)NE * FE / 2 * HID];
// pre-split intermediates (written by FUSE epilogues)
__device__ uint32_t g_ish[(size_t)T_TOK * FS / 2],  g_isl[(size_t)T_TOK * FS / 2];
__device__ uint32_t g_irh[(size_t)NPAIR * FE / 2],  g_irl[(size_t)NPAIR * FE / 2];

// ---------------------------------------------------------------------------
// fp16 hi/lo split (validated R10/R11)
// ---------------------------------------------------------------------------
__device__ __forceinline__ void split_h2(float x, float y,
                                         uint32_t& hi, uint32_t& lo) {
    half hx = __float2half_rn(x);
    half hy = __float2half_rn(y);
    half lx = __float2half_rn(x - __half2float(hx));
    half ly = __float2half_rn(y - __half2float(hy));
    __half2 h = __halves2half2(hx, hy);
    __half2 l = __halves2half2(lx, ly);
    hi = *reinterpret_cast<uint32_t*>(&h);
    lo = *reinterpret_cast<uint32_t*>(&l);
}

__device__ __forceinline__ void mma_f16(float* d,
                                        const uint32_t* a,
                                        const uint32_t* b) {
    asm volatile(
        "mma.sync.aligned.m16n8k16.row.col.f32.f16.f16.f32 "
        "{%0,%1,%2,%3}, {%4,%5,%6,%7}, {%8,%9}, {%0,%1,%2,%3};\n"
        : "+f"(d[0]), "+f"(d[1]), "+f"(d[2]), "+f"(d[3])
        : "r"(a[0]), "r"(a[1]), "r"(a[2]), "r"(a[3]),
          "r"(b[0]), "r"(b[1]));
}

__device__ __forceinline__ void cp_async16(uint32_t dst, const void* src,
                                           int src_bytes) {
    asm volatile("cp.async.cg.shared.global [%0], [%1], 16, %2;\n"
                 :: "r"(dst), "l"(src), "r"(src_bytes) : "memory");
}
#define CP_COMMIT() asm volatile("cp.async.commit_group;" ::: "memory")
#define CP_WAIT2()  asm volatile("cp.async.wait_group 2;" ::: "memory")

__device__ __forceinline__ uint32_t cvta_smem(const void* p) {
    uint32_t a;
    asm("{ .reg .u64 t; cvta.to.shared.u64 t, %1; cvt.u32.u64 %0, t; }"
        : "=r"(a) : "l"(p));
    return a;
}

// ---------------------------------------------------------------------------
// Splitters — 4 words/thread, unrolled (MLP 8)
// ---------------------------------------------------------------------------
__global__ void split_contig_kernel(const float* __restrict__ src,
                                    uint32_t* __restrict__ hi,
                                    uint32_t* __restrict__ lo, int nwords) {
    int i = (blockIdx.x * 256 + threadIdx.x) * 4;
    if (i >= nwords) return;
    float2 v0 = ((const float2*)src)[i];
    float2 v1 = ((const float2*)src)[i + 1];
    float2 v2 = ((const float2*)src)[i + 2];
    float2 v3 = ((const float2*)src)[i + 3];
    uint4 h, l;
    split_h2(v0.x, v0.y, h.x, l.x);
    split_h2(v1.x, v1.y, h.y, l.y);
    split_h2(v2.x, v2.y, h.z, l.z);
    split_h2(v3.x, v3.y, h.w, l.w);
    *(uint4*)(hi + i) = h;
    *(uint4*)(lo + i) = l;
}
// pairs along K (row stride N): word(kp,n) = half2(src[2kp][n], src[2kp+1][n])
__global__ void split_strided_kernel(const float* __restrict__ src,
                                     uint32_t* __restrict__ hi,
                                     uint32_t* __restrict__ lo,
                                     int nwords, int N) {
    int i = (blockIdx.x * 256 + threadIdx.x) * 4;
    if (i >= nwords) return;
    int kp = i / N, n = i - kp * N;  // N % 4 == 0 -> all 4 words share kp
    float4 a = *(const float4*)(src + (size_t)(2 * kp) * N + n);
    float4 b = *(const float4*)(src + (size_t)(2 * kp + 1) * N + n);
    uint4 h, l;
    split_h2(a.x, b.x, h.x, l.x);
    split_h2(a.y, b.y, h.y, l.y);
    split_h2(a.z, b.z, h.z, l.z);
    split_h2(a.w, b.w, h.w, l.w);
    *(uint4*)(hi + i) = h;
    *(uint4*)(lo + i) = l;
}

// ---------------------------------------------------------------------------
// Router (validated rounds 1-11)
// ---------------------------------------------------------------------------
__global__ void zero_counts_kernel() {
    if (threadIdx.x < NE) g_cnt[threadIdx.x] = 0;
}

__global__ void router_kernel(const float* __restrict__ x,
                              const float* __restrict__ rw) {
    int warp = threadIdx.x >> 5;
    int lane = threadIdx.x & 31;
    int t = blockIdx.x * (blockDim.x >> 5) + warp;
    if (t >= T_TOK) return;

    float acc[NE];
#pragma unroll
    for (int e = 0; e < NE; e++) acc[e] = 0.0f;

    const float* xr = x + (size_t)t * HID;
    for (int d = lane; d < HID; d += 32) {
        float xv = xr[d];
        const float* r = rw + (size_t)d * NE;
#pragma unroll
        for (int e = 0; e < NE; e++) acc[e] = fmaf(xv, r[e], acc[e]);
    }
#pragma unroll
    for (int e = 0; e < NE; e++) {
#pragma unroll
        for (int off = 16; off; off >>= 1)
            acc[e] += __shfl_xor_sync(0xffffffffu, acc[e], off);
    }

    if (lane == 0) {
        float mx = acc[0];
#pragma unroll
        for (int e = 1; e < NE; e++) mx = fmaxf(mx, acc[e]);
        float p[NE];
        float s = 0.0f;
#pragma unroll
        for (int e = 0; e < NE; e++) { p[e] = expf(acc[e] - mx); s += p[e]; }
        float inv = 1.0f / s;
#pragma unroll
        for (int e = 0; e < NE; e++) p[e] *= inv;

        int   i0 = 0; float w0 = p[0];
#pragma unroll
        for (int e = 1; e < NE; e++) if (p[e] > w0) { w0 = p[e]; i0 = e; }
        int   i1 = -1; float w1 = -1.0f;
#pragma unroll
        for (int e = 0; e < NE; e++)
            if (e != i0 && p[e] > w1) { w1 = p[e]; i1 = e; }

        int pos0 = atomicAdd(&g_cnt[i0], 1);
        g_bucket[i0 * T_TOK + pos0] = 2 * t;
        int pos1 = atomicAdd(&g_cnt[i1], 1);
        g_bucket[i1 * T_TOK + pos1] = 2 * t + 1;
        g_pw[2 * t]     = w0;
        g_pw[2 * t + 1] = w1;
    }
}

// ---------------------------------------------------------------------------
// Tensor GEMM 128x128x16, 256 threads, pre-split fp16 inputs, cp.async
// 4-stage pipeline (issue-ahead 3, wait_group 2), m16n8k16 HMMA.
// A gmem: [rows][K/2] half2 words.  B gmem: [K/2][N] half2 words.
// Smem words/stage: Ah [128][12] @0, Al @1536, Bh [8][136] @3072, Bl @4160.
// MODE 0: plain. MODE 1: gather x rows by pair>>1, scatter C by pair.
// MODE 2: gather rows by pair, scale by router weight, atomicAdd into
//         C[token] (token = pair>>1) — fuses the final pair-sum.
// FUSE 1: write CH/CL = split(silu(G) * acc) instead of C.
// ---------------------------------------------------------------------------
#define BM 128
#define BN 128
#define BK 16
#define A_PAD 12
#define B_PAD 136
#define OFF_AL 1536
#define OFF_BH 3072
#define OFF_BL 4160
#define STAGEF 5248
#define NSTG 4
#define SMEM_DYN (NSTG * STAGEF * 4)

template <int MODE, int FUSE>
__global__ __launch_bounds__(256, 2)
void tgemm_kernel(const uint32_t* __restrict__ Ahg,
                  const uint32_t* __restrict__ Alg,
                  const uint32_t* __restrict__ Bhg,
                  const uint32_t* __restrict__ Blg,
                  float* __restrict__ C,
                  uint32_t* __restrict__ CH,
                  uint32_t* __restrict__ CL,
                  const float* __restrict__ G,
                  int M, int N, int K) {
    const int e = blockIdx.z;
    int m_rows = M;
    const int* rowlist = nullptr;
    if (MODE != 0) {
        m_rows  = g_cnt[e];
        rowlist = g_bucket + e * T_TOK;
        Bhg += (size_t)e * (K / 2) * N;
        Blg += (size_t)e * (K / 2) * N;
    }
    const int m0 = blockIdx.y * BM;
    const int n0 = blockIdx.x * BN;
    if (m0 >= m_rows) return;

    extern __shared__ uint32_t sm[];
    const uint32_t smem_base = cvta_smem(sm);

    const int tid  = threadIdx.x;
    const int lane = tid & 31;
    const int wid  = tid >> 5;
    const int warp_m = wid >> 2;
    const int warp_n = wid & 3;
    const int g  = lane >> 2;
    const int t4 = lane & 3;
    const int mb = warp_m * 64;
    const int nb = warp_n * 32;

    const int KW = K / 2;

    const int am     = tid >> 1;
    const int achunk = (tid & 1) * 4;
    const int bkp    = tid >> 5;
    const int bc4    = (tid & 31) * 4;

    const int  ar_g = m0 + am;
    const bool av   = ar_g < m_rows;
    const int  aidx = av ? ar_g : 0;
    int rowidx;
    if (MODE == 0)      rowidx = aidx;
    else if (MODE == 1) rowidx = rowlist[aidx] >> 1;
    else                rowidx = rowlist[aidx];
    const uint32_t* ArH = Ahg + (size_t)rowidx * KW + achunk;
    const uint32_t* ArL = Alg + (size_t)rowidx * KW + achunk;
    const uint32_t* BgH = Bhg + (size_t)bkp * N + n0 + bc4;
    const uint32_t* BgL = Blg + (size_t)bkp * N + n0 + bc4;
    const int abytes = av ? 16 : 0;

    const uint32_t a_dst  = smem_base + (am * A_PAD + achunk) * 4;
    const uint32_t b_dst  = smem_base + (bkp * B_PAD + bc4) * 4;
    const int KT = K / BK;

    auto issue_stage = [&](int kt) {
        const uint32_t so = (uint32_t)((kt % NSTG) * (STAGEF * 4));
        const int kw0 = kt * 8;
        cp_async16(a_dst + so,              ArH + kw0, abytes);
        cp_async16(a_dst + so + OFF_AL * 4, ArL + kw0, abytes);
        cp_async16(b_dst + so + OFF_BH * 4, BgH + (size_t)kw0 * N, 16);
        cp_async16(b_dst + so + OFF_BL * 4, BgL + (size_t)kw0 * N, 16);
    };

    // Prologue: stages 0..2
    issue_stage(0); CP_COMMIT();
    issue_stage(1); CP_COMMIT();
    issue_stage(2); CP_COMMIT();

    float acc[4][4][4];
#pragma unroll
    for (int i = 0; i < 4; i++)
#pragma unroll
        for (int j = 0; j < 4; j++)
#pragma unroll
            for (int r = 0; r < 4; r++) acc[i][j][r] = 0.0f;

    for (int kt = 0; kt < KT; kt++) {
        CP_WAIT2();
        __syncthreads();
        if (kt + 3 < KT) issue_stage(kt + 3);
        CP_COMMIT();

        const uint32_t* Ah = sm + (kt % NSTG) * STAGEF;
        const uint32_t* Al = Ah + OFF_AL;
        const uint32_t* Bh = sm + (kt % NSTG) * STAGEF + OFF_BH;
        const uint32_t* Bl = Bh + (OFF_BL - OFF_BH);

        uint32_t bh[4][2], bl[4][2];
#pragma unroll
        for (int nt = 0; nt < 4; nt++) {
            const int col = nb + nt * 8 + g;
            bh[nt][0] = Bh[t4 * B_PAD + col];
            bh[nt][1] = Bh[(t4 + 4) * B_PAD + col];
            bl[nt][0] = Bl[t4 * B_PAD + col];
            bl[nt][1] = Bl[(t4 + 4) * B_PAD + col];
        }
#pragma unroll
        for (int mt = 0; mt < 4; mt++) {
            const int r0 = (mb + mt * 16 + g) * A_PAD;
            const int r1 = r0 + 8 * A_PAD;
            uint32_t ah[4], al[4];
            ah[0] = Ah[r0 + t4];
            ah[1] = Ah[r1 + t4];
            ah[2] = Ah[r0 + t4 + 4];
            ah[3] = Ah[r1 + t4 + 4];
            al[0] = Al[r0 + t4];
            al[1] = Al[r1 + t4];
            al[2] = Al[r0 + t4 + 4];
            al[3] = Al[r1 + t4 + 4];
#pragma unroll
            for (int nt = 0; nt < 4; nt++) mma_f16(acc[mt][nt], ah, bh[nt]);
#pragma unroll
            for (int nt = 0; nt < 4; nt++) mma_f16(acc[mt][nt], ah, bl[nt]);
#pragma unroll
            for (int nt = 0; nt < 4; nt++) mma_f16(acc[mt][nt], al, bh[nt]);
        }
    }

    // Epilogue
#pragma unroll
    for (int mt = 0; mt < 4; mt++) {
        const int r0 = m0 + mb + mt * 16 + g;
        const int r1 = r0 + 8;
        size_t ro0 = 0, ro1 = 0;
        bool v0 = r0 < m_rows, v1 = r1 < m_rows;
        float s0 = 1.0f, s1 = 1.0f;
        if (v0) {
            if (MODE == 0) ro0 = (size_t)r0 * N;
            else {
                const int p = rowlist[r0];
                if (MODE == 2) { s0 = g_pw[p]; ro0 = (size_t)(p >> 1) * N; }
                else ro0 = (size_t)p * N;
            }
        }
        if (v1) {
            if (MODE == 0) ro1 = (size_t)r1 * N;
            else {
                const int p = rowlist[r1];
                if (MODE == 2) { s1 = g_pw[p]; ro1 = (size_t)(p >> 1) * N; }
                else ro1 = (size_t)p * N;
            }
        }
#pragma unroll
        for (int nt = 0; nt < 4; nt++) {
            const int c = n0 + nb + nt * 8 + 2 * t4;
            if (v0) {
                float o0 = acc[mt][nt][0] * s0, o1 = acc[mt][nt][1] * s0;
                if (FUSE) {
                    float2 gv = *(const float2*)(G + ro0 + c);
                    o0 *= gv.x / (1.0f + expf(-gv.x));
                    o1 *= gv.y / (1.0f + expf(-gv.y));
                    uint32_t h, l;
                    split_h2(o0, o1, h, l);
                    const size_t wi = (ro0 + c) >> 1;
                    CH[wi] = h; CL[wi] = l;
                } else if (MODE == 2) {
                    atomicAdd(C + ro0 + c, o0);
                    atomicAdd(C + ro0 + c + 1, o1);
                } else {
                    *(float2*)(C + ro0 + c) = make_float2(o0, o1);
                }
            }
            if (v1) {
                float o0 = acc[mt][nt][2] * s1, o1 = acc[mt][nt][3] * s1;
                if (FUSE) {
                    float2 gv = *(const float2*)(G + ro1 + c);
                    o0 *= gv.x / (1.0f + expf(-gv.x));
                    o1 *= gv.y / (1.0f + expf(-gv.y));
                    uint32_t h, l;
                    split_h2(o0, o1, h, l);
                    const size_t wi = (ro1 + c) >> 1;
                    CH[wi] = h; CL[wi] = l;
                } else if (MODE == 2) {
                    atomicAdd(C + ro1 + c, o0);
                    atomicAdd(C + ro1 + c + 1, o1);
                } else {
                    *(float2*)(C + ro1 + c) = make_float2(o0, o1);
                }
            }
        }
    }
}

// ---------------------------------------------------------------------------
// Launch
// ---------------------------------------------------------------------------
extern "C" void kernel_launch(void* const* d_in, const int* in_sizes, int n_in,
                              void* d_out, int out_size) {
    const float* x  = (const float*)d_in[0];
    const float* rw = (const float*)d_in[1];
    const float* eg = (const float*)d_in[2];
    const float* eu = (const float*)d_in[3];
    const float* ed = (const float*)d_in[4];
    const float* sg = (const float*)d_in[5];
    const float* su = (const float*)d_in[6];
    const float* sd = (const float*)d_in[7];
    float* out = (float*)d_out;

#define SYM(p, s) void* p; cudaGetSymbolAddress(&p, s)
    SYM(p_gate_s, g_gate_s); SYM(p_gate_r, g_gate_r);
    SYM(p_xh, g_xh);   SYM(p_xl, g_xl);
    SYM(p_sgh, g_sgh); SYM(p_sgl, g_sgl);
    SYM(p_suh, g_suh); SYM(p_sul, g_sul);
    SYM(p_sdh, g_sdh); SYM(p_sdl, g_sdl);
    SYM(p_egh, g_egh); SYM(p_egl, g_egl);
    SYM(p_euh, g_euh); SYM(p_eul, g_eul);
    SYM(p_edh, g_edh); SYM(p_edl, g_edl);
    SYM(p_ish, g_ish); SYM(p_isl, g_isl);
    SYM(p_irh, g_irh); SYM(p_irl, g_irl);
#undef SYM

    cudaFuncSetAttribute(tgemm_kernel<0, 0>,
                         cudaFuncAttributeMaxDynamicSharedMemorySize, SMEM_DYN);
    cudaFuncSetAttribute(tgemm_kernel<0, 1>,
                         cudaFuncAttributeMaxDynamicSharedMemorySize, SMEM_DYN);
    cudaFuncSetAttribute(tgemm_kernel<1, 0>,
                         cudaFuncAttributeMaxDynamicSharedMemorySize, SMEM_DYN);
    cudaFuncSetAttribute(tgemm_kernel<1, 1>,
                         cudaFuncAttributeMaxDynamicSharedMemorySize, SMEM_DYN);
    cudaFuncSetAttribute(tgemm_kernel<2, 0>,
                         cudaFuncAttributeMaxDynamicSharedMemorySize, SMEM_DYN);

    zero_counts_kernel<<<1, 32>>>();
    router_kernel<<<T_TOK / 4, 128>>>(x, rw);

    // Pre-split inputs (4 words/thread)
    split_contig_kernel<<<(T_TOK * HID / 2 / 4) / 256, 256>>>(
        x, (uint32_t*)p_xh, (uint32_t*)p_xl, T_TOK * HID / 2);
    split_strided_kernel<<<(HID / 2 * FS / 4) / 256, 256>>>(
        sg, (uint32_t*)p_sgh, (uint32_t*)p_sgl, HID / 2 * FS, FS);
    split_strided_kernel<<<(HID / 2 * FS / 4) / 256, 256>>>(
        su, (uint32_t*)p_suh, (uint32_t*)p_sul, HID / 2 * FS, FS);
    split_strided_kernel<<<(FS / 2 * HID / 4) / 256, 256>>>(
        sd, (uint32_t*)p_sdh, (uint32_t*)p_sdl, FS / 2 * HID, HID);
    split_strided_kernel<<<(NE * HID / 2 * FE / 4) / 256, 256>>>(
        eg, (uint32_t*)p_egh, (uint32_t*)p_egl, NE * HID / 2 * FE, FE);
    split_strided_kernel<<<(NE * HID / 2 * FE / 4) / 256, 256>>>(
        eu, (uint32_t*)p_euh, (uint32_t*)p_eul, NE * HID / 2 * FE, FE);
    split_strided_kernel<<<(NE * FE / 2 * HID / 4) / 256, 256>>>(
        ed, (uint32_t*)p_edh, (uint32_t*)p_edl, NE * FE / 2 * HID, HID);

    // Shared expert: gate -> (up, silu fused, split-write) -> down (writes out)
    tgemm_kernel<0, 0><<<dim3(FS / BN, T_TOK / BM, 1), 256, SMEM_DYN>>>(
        (const uint32_t*)p_xh, (const uint32_t*)p_xl,
        (const uint32_t*)p_sgh, (const uint32_t*)p_sgl,
        (float*)p_gate_s, nullptr, nullptr, nullptr, T_TOK, FS, HID);
    tgemm_kernel<0, 1><<<dim3(FS / BN, T_TOK / BM, 1), 256, SMEM_DYN>>>(
        (const uint32_t*)p_xh, (const uint32_t*)p_xl,
        (const uint32_t*)p_suh, (const uint32_t*)p_sul,
        nullptr, (uint32_t*)p_ish, (uint32_t*)p_isl,
        (const float*)p_gate_s, T_TOK, FS, HID);
    tgemm_kernel<0, 0><<<dim3(HID / BN, T_TOK / BM, 1), 256, SMEM_DYN>>>(
        (const uint32_t*)p_ish, (const uint32_t*)p_isl,
        (const uint32_t*)p_sdh, (const uint32_t*)p_sdl,
        out, nullptr, nullptr, nullptr, T_TOK, HID, FS);

    // Routed experts: gate -> (up, silu fused) -> down (atomicAdd into out)
    tgemm_kernel<1, 0><<<dim3(FE / BN, T_TOK / BM, NE), 256, SMEM_DYN>>>(
        (const uint32_t*)p_xh, (const uint32_t*)p_xl,
        (const uint32_t*)p_egh, (const uint32_t*)p_egl,
        (float*)p_gate_r, nullptr, nullptr, nullptr, 0, FE, HID);
    tgemm_kernel<1, 1><<<dim3(FE / BN, T_TOK / BM, NE), 256, SMEM_DYN>>>(
        (const uint32_t*)p_xh, (const uint32_t*)p_xl,
        (const uint32_t*)p_euh, (const uint32_t*)p_eul,
        nullptr, (uint32_t*)p_irh, (uint32_t*)p_irl,
        (const float*)p_gate_r, 0, FE, HID);
    tgemm_kernel<2, 0><<<dim3(HID / BN, T_TOK / BM, NE), 256, SMEM_DYN>>>(
        (const uint32_t*)p_irh, (const uint32_t*)p_irl,
        (const uint32_t*)p_edh, (const uint32_t*)p_edl,
        out, nullptr, nullptr, nullptr, 0, HID, FE);
}

// round 13
// speedup vs baseline: 1.8856x; 1.0401x over previous
#include <cuda_runtime.h>
#include <cuda_fp16.h>
#include <math.h>
#include <stdint.h>

// Problem constants (fixed by the dataset)
#define T_TOK 4096
#define HID   1024
#define NE    16
#define FE    512
#define FS    2048
#define NPAIR (T_TOK * 2)

// ---------------------------------------------------------------------------
// Scratch (all half2-packed words are uint32)
// ---------------------------------------------------------------------------
__device__ float    g_gate_s[(size_t)T_TOK * FS];
__device__ float    g_gate_r[(size_t)NPAIR * FE];
__device__ int      g_cnt[NE];
__device__ int      g_bucket[NE * T_TOK];
__device__ float    g_pw[NPAIR];
// pre-split inputs (hi/lo fp16, half2-packed along K)
__device__ uint32_t g_xh[(size_t)T_TOK * HID / 2];
__device__ uint32_t g_xl[(size_t)T_TOK * HID / 2];
__device__ uint32_t g_sgh[(size_t)HID / 2 * FS],  g_sgl[(size_t)HID / 2 * FS];
__device__ uint32_t g_suh[(size_t)HID / 2 * FS],  g_sul[(size_t)HID / 2 * FS];
__device__ uint32_t g_sdh[(size_t)FS / 2 * HID],  g_sdl[(size_t)FS / 2 * HID];
__device__ uint32_t g_egh[(size_t)NE * HID / 2 * FE], g_egl[(size_t)NE * HID / 2 * FE];
__device__ uint32_t g_euh[(size_t)NE * HID / 2 * FE], g_eul[(size_t)NE * HID / 2 * FE];
__device__ uint32_t g_edh[(size_t)NE * FE / 2 * HID], g_edl[(size_t)NE * FE / 2 * HID];
// pre-split intermediates (written by FUSE epilogues)
__device__ uint32_t g_ish[(size_t)T_TOK * FS / 2],  g_isl[(size_t)T_TOK * FS / 2];
__device__ uint32_t g_irh[(size_t)NPAIR * FE / 2],  g_irl[(size_t)NPAIR * FE / 2];

// ---------------------------------------------------------------------------
// fp16 hi/lo split (validated R10-R12)
// ---------------------------------------------------------------------------
__device__ __forceinline__ void split_h2(float x, float y,
                                         uint32_t& hi, uint32_t& lo) {
    half hx = __float2half_rn(x);
    half hy = __float2half_rn(y);
    half lx = __float2half_rn(x - __half2float(hx));
    half ly = __float2half_rn(y - __half2float(hy));
    __half2 h = __halves2half2(hx, hy);
    __half2 l = __halves2half2(lx, ly);
    hi = *reinterpret_cast<uint32_t*>(&h);
    lo = *reinterpret_cast<uint32_t*>(&l);
}

__device__ __forceinline__ void mma_f16(float* d,
                                        const uint32_t* a,
                                        const uint32_t* b) {
    asm volatile(
        "mma.sync.aligned.m16n8k16.row.col.f32.f16.f16.f32 "
        "{%0,%1,%2,%3}, {%4,%5,%6,%7}, {%8,%9}, {%0,%1,%2,%3};\n"
        : "+f"(d[0]), "+f"(d[1]), "+f"(d[2]), "+f"(d[3])
        : "r"(a[0]), "r"(a[1]), "r"(a[2]), "r"(a[3]),
          "r"(b[0]), "r"(b[1]));
}

// ldmatrix x4: loads a 16x16 fp16 tile as the exact m16n8k16 A fragment
#define LDSM_X4(r0, r1, r2, r3, addr) \
    asm volatile("ldmatrix.sync.aligned.m8n8.x4.shared.b16 {%0,%1,%2,%3}, [%4];" \
                 : "=r"(r0), "=r"(r1), "=r"(r2), "=r"(r3) : "r"(addr))

__device__ __forceinline__ void cp_async16(uint32_t dst, const void* src,
                                           int src_bytes) {
    asm volatile("cp.async.cg.shared.global [%0], [%1], 16, %2;\n"
                 :: "r"(dst), "l"(src), "r"(src_bytes) : "memory");
}
#define CP_COMMIT() asm volatile("cp.async.commit_group;" ::: "memory")
#define CP_WAIT2()  asm volatile("cp.async.wait_group 2;" ::: "memory")

__device__ __forceinline__ uint32_t cvta_smem(const void* p) {
    uint32_t a;
    asm("{ .reg .u64 t; cvta.to.shared.u64 t, %1; cvt.u32.u64 %0, t; }"
        : "=r"(a) : "l"(p));
    return a;
}

// ---------------------------------------------------------------------------
// Splitters — 4 words/thread (validated R12)
// ---------------------------------------------------------------------------
__global__ void split_contig_kernel(const float* __restrict__ src,
                                    uint32_t* __restrict__ hi,
                                    uint32_t* __restrict__ lo, int nwords) {
    int i = (blockIdx.x * 256 + threadIdx.x) * 4;
    if (i >= nwords) return;
    float2 v0 = ((const float2*)src)[i];
    float2 v1 = ((const float2*)src)[i + 1];
    float2 v2 = ((const float2*)src)[i + 2];
    float2 v3 = ((const float2*)src)[i + 3];
    uint4 h, l;
    split_h2(v0.x, v0.y, h.x, l.x);
    split_h2(v1.x, v1.y, h.y, l.y);
    split_h2(v2.x, v2.y, h.z, l.z);
    split_h2(v3.x, v3.y, h.w, l.w);
    *(uint4*)(hi + i) = h;
    *(uint4*)(lo + i) = l;
}
__global__ void split_strided_kernel(const float* __restrict__ src,
                                     uint32_t* __restrict__ hi,
                                     uint32_t* __restrict__ lo,
                                     int nwords, int N) {
    int i = (blockIdx.x * 256 + threadIdx.x) * 4;
    if (i >= nwords) return;
    int kp = i / N, n = i - kp * N;
    float4 a = *(const float4*)(src + (size_t)(2 * kp) * N + n);
    float4 b = *(const float4*)(src + (size_t)(2 * kp + 1) * N + n);
    uint4 h, l;
    split_h2(a.x, b.x, h.x, l.x);
    split_h2(a.y, b.y, h.y, l.y);
    split_h2(a.z, b.z, h.z, l.z);
    split_h2(a.w, b.w, h.w, l.w);
    *(uint4*)(hi + i) = h;
    *(uint4*)(lo + i) = l;
}

// ---------------------------------------------------------------------------
// Router (validated rounds 1-12)
// ---------------------------------------------------------------------------
__global__ void zero_counts_kernel() {
    if (threadIdx.x < NE) g_cnt[threadIdx.x] = 0;
}

__global__ void router_kernel(const float* __restrict__ x,
                              const float* __restrict__ rw) {
    int warp = threadIdx.x >> 5;
    int lane = threadIdx.x & 31;
    int t = blockIdx.x * (blockDim.x >> 5) + warp;
    if (t >= T_TOK) return;

    float acc[NE];
#pragma unroll
    for (int e = 0; e < NE; e++) acc[e] = 0.0f;

    const float* xr = x + (size_t)t * HID;
    for (int d = lane; d < HID; d += 32) {
        float xv = xr[d];
        const float* r = rw + (size_t)d * NE;
#pragma unroll
        for (int e = 0; e < NE; e++) acc[e] = fmaf(xv, r[e], acc[e]);
    }
#pragma unroll
    for (int e = 0; e < NE; e++) {
#pragma unroll
        for (int off = 16; off; off >>= 1)
            acc[e] += __shfl_xor_sync(0xffffffffu, acc[e], off);
    }

    if (lane == 0) {
        float mx = acc[0];
#pragma unroll
        for (int e = 1; e < NE; e++) mx = fmaxf(mx, acc[e]);
        float p[NE];
        float s = 0.0f;
#pragma unroll
        for (int e = 0; e < NE; e++) { p[e] = expf(acc[e] - mx); s += p[e]; }
        float inv = 1.0f / s;
#pragma unroll
        for (int e = 0; e < NE; e++) p[e] *= inv;

        int   i0 = 0; float w0 = p[0];
#pragma unroll
        for (int e = 1; e < NE; e++) if (p[e] > w0) { w0 = p[e]; i0 = e; }
        int   i1 = -1; float w1 = -1.0f;
#pragma unroll
        for (int e = 0; e < NE; e++)
            if (e != i0 && p[e] > w1) { w1 = p[e]; i1 = e; }

        int pos0 = atomicAdd(&g_cnt[i0], 1);
        g_bucket[i0 * T_TOK + pos0] = 2 * t;
        int pos1 = atomicAdd(&g_cnt[i1], 1);
        g_bucket[i1 * T_TOK + pos1] = 2 * t + 1;
        g_pw[2 * t]     = w0;
        g_pw[2 * t + 1] = w1;
    }
}

// ---------------------------------------------------------------------------
// Tensor GEMM 128x128x16, 256 threads, pre-split fp16 inputs, cp.async
// 4-stage pipeline, m16n8k16 HMMA. A fragments via ldmatrix.x4
// (8 LDSM replace 32 LDS.32 per warp-ktile; layout verified conflict-free:
//  rows stride 12 words -> starts {0,12,24,4,16,28,8,20} tile banks 0-31).
// MODE 0: plain. MODE 1: gather x rows by pair>>1, scatter C by pair.
// MODE 2: gather rows by pair, scale by router weight, atomicAdd into
//         C[token] (token = pair>>1).
// FUSE 1: write CH/CL = split(silu(G) * acc) instead of C.
// ---------------------------------------------------------------------------
#define BM 128
#define BN 128
#define BK 16
#define A_PAD 12
#define B_PAD 136
#define OFF_AL 1536
#define OFF_BH 3072
#define OFF_BL 4160
#define STAGEF 5248
#define NSTG 4
#define SMEM_DYN (NSTG * STAGEF * 4)

template <int MODE, int FUSE>
__global__ __launch_bounds__(256, 2)
void tgemm_kernel(const uint32_t* __restrict__ Ahg,
                  const uint32_t* __restrict__ Alg,
                  const uint32_t* __restrict__ Bhg,
                  const uint32_t* __restrict__ Blg,
                  float* __restrict__ C,
                  uint32_t* __restrict__ CH,
                  uint32_t* __restrict__ CL,
                  const float* __restrict__ G,
                  int M, int N, int K) {
    const int e = blockIdx.z;
    int m_rows = M;
    const int* rowlist = nullptr;
    if (MODE != 0) {
        m_rows  = g_cnt[e];
        rowlist = g_bucket + e * T_TOK;
        Bhg += (size_t)e * (K / 2) * N;
        Blg += (size_t)e * (K / 2) * N;
    }
    const int m0 = blockIdx.y * BM;
    const int n0 = blockIdx.x * BN;
    if (m0 >= m_rows) return;

    extern __shared__ uint32_t sm[];
    const uint32_t smem_base = cvta_smem(sm);

    const int tid  = threadIdx.x;
    const int lane = tid & 31;
    const int wid  = tid >> 5;
    const int warp_m = wid >> 2;
    const int warp_n = wid & 3;
    const int g  = lane >> 2;
    const int t4 = lane & 3;
    const int mb = warp_m * 64;
    const int nb = warp_n * 32;

    const int KW = K / 2;

    const int am     = tid >> 1;
    const int achunk = (tid & 1) * 4;
    const int bkp    = tid >> 5;
    const int bc4    = (tid & 31) * 4;

    const int  ar_g = m0 + am;
    const bool av   = ar_g < m_rows;
    const int  aidx = av ? ar_g : 0;
    int rowidx;
    if (MODE == 0)      rowidx = aidx;
    else if (MODE == 1) rowidx = rowlist[aidx] >> 1;
    else                rowidx = rowlist[aidx];
    const uint32_t* ArH = Ahg + (size_t)rowidx * KW + achunk;
    const uint32_t* ArL = Alg + (size_t)rowidx * KW + achunk;
    const uint32_t* BgH = Bhg + (size_t)bkp * N + n0 + bc4;
    const uint32_t* BgL = Blg + (size_t)bkp * N + n0 + bc4;
    const int abytes = av ? 16 : 0;

    const uint32_t a_dst  = smem_base + (am * A_PAD + achunk) * 4;
    const uint32_t b_dst  = smem_base + (bkp * B_PAD + bc4) * 4;
    const int KT = K / BK;

    // ldmatrix per-lane source address within the A tile of a stage:
    // lane group sel = lane>>3 picks 8x8 tile: (m-half = sel&1, k-half = sel>>1)
    const int sel = lane >> 3;
    const int rr  = lane & 7;
    const uint32_t a_lm_base =
        (uint32_t)(((mb + rr + ((sel & 1) << 3)) * A_PAD + ((sel >> 1) << 2)) * 4);

    auto issue_stage = [&](int kt) {
        const uint32_t so = (uint32_t)((kt % NSTG) * (STAGEF * 4));
        const int kw0 = kt * 8;
        cp_async16(a_dst + so,              ArH + kw0, abytes);
        cp_async16(a_dst + so + OFF_AL * 4, ArL + kw0, abytes);
        cp_async16(b_dst + so + OFF_BH * 4, BgH + (size_t)kw0 * N, 16);
        cp_async16(b_dst + so + OFF_BL * 4, BgL + (size_t)kw0 * N, 16);
    };

    issue_stage(0); CP_COMMIT();
    issue_stage(1); CP_COMMIT();
    issue_stage(2); CP_COMMIT();

    float acc[4][4][4];
#pragma unroll
    for (int i = 0; i < 4; i++)
#pragma unroll
        for (int j = 0; j < 4; j++)
#pragma unroll
            for (int r = 0; r < 4; r++) acc[i][j][r] = 0.0f;

    for (int kt = 0; kt < KT; kt++) {
        CP_WAIT2();
        __syncthreads();
        if (kt + 3 < KT) issue_stage(kt + 3);
        CP_COMMIT();

        const uint32_t stage_b = smem_base + (uint32_t)((kt % NSTG) * (STAGEF * 4));
        const uint32_t* Bh = sm + (kt % NSTG) * STAGEF + OFF_BH;
        const uint32_t* Bl = Bh + (OFF_BL - OFF_BH);

        uint32_t bh[4][2], bl[4][2];
#pragma unroll
        for (int nt = 0; nt < 4; nt++) {
            const int col = nb + nt * 8 + g;
            bh[nt][0] = Bh[t4 * B_PAD + col];
            bh[nt][1] = Bh[(t4 + 4) * B_PAD + col];
            bl[nt][0] = Bl[t4 * B_PAD + col];
            bl[nt][1] = Bl[(t4 + 4) * B_PAD + col];
        }
#pragma unroll
        for (int mt = 0; mt < 4; mt++) {
            const uint32_t a_addr = stage_b + a_lm_base
                                  + (uint32_t)(mt * 16 * A_PAD * 4);
            uint32_t ah[4], al[4];
            LDSM_X4(ah[0], ah[1], ah[2], ah[3], a_addr);
            LDSM_X4(al[0], al[1], al[2], al[3], a_addr + OFF_AL * 4);
#pragma unroll
            for (int nt = 0; nt < 4; nt++) mma_f16(acc[mt][nt], ah, bh[nt]);
#pragma unroll
            for (int nt = 0; nt < 4; nt++) mma_f16(acc[mt][nt], ah, bl[nt]);
#pragma unroll
            for (int nt = 0; nt < 4; nt++) mma_f16(acc[mt][nt], al, bh[nt]);
        }
    }

    // Epilogue (validated R12)
#pragma unroll
    for (int mt = 0; mt < 4; mt++) {
        const int r0 = m0 + mb + mt * 16 + g;
        const int r1 = r0 + 8;
        size_t ro0 = 0, ro1 = 0;
        bool v0 = r0 < m_rows, v1 = r1 < m_rows;
        float s0 = 1.0f, s1 = 1.0f;
        if (v0) {
            if (MODE == 0) ro0 = (size_t)r0 * N;
            else {
                const int p = rowlist[r0];
                if (MODE == 2) { s0 = g_pw[p]; ro0 = (size_t)(p >> 1) * N; }
                else ro0 = (size_t)p * N;
            }
        }
        if (v1) {
            if (MODE == 0) ro1 = (size_t)r1 * N;
            else {
                const int p = rowlist[r1];
                if (MODE == 2) { s1 = g_pw[p]; ro1 = (size_t)(p >> 1) * N; }
                else ro1 = (size_t)p * N;
            }
        }
#pragma unroll
        for (int nt = 0; nt < 4; nt++) {
            const int c = n0 + nb + nt * 8 + 2 * t4;
            if (v0) {
                float o0 = acc[mt][nt][0] * s0, o1 = acc[mt][nt][1] * s0;
                if (FUSE) {
                    float2 gv = *(const float2*)(G + ro0 + c);
                    o0 *= gv.x / (1.0f + expf(-gv.x));
                    o1 *= gv.y / (1.0f + expf(-gv.y));
                    uint32_t h, l;
                    split_h2(o0, o1, h, l);
                    const size_t wi = (ro0 + c) >> 1;
                    CH[wi] = h; CL[wi] = l;
                } else if (MODE == 2) {
                    atomicAdd(C + ro0 + c, o0);
                    atomicAdd(C + ro0 + c + 1, o1);
                } else {
                    *(float2*)(C + ro0 + c) = make_float2(o0, o1);
                }
            }
            if (v1) {
                float o0 = acc[mt][nt][2] * s1, o1 = acc[mt][nt][3] * s1;
                if (FUSE) {
                    float2 gv = *(const float2*)(G + ro1 + c);
                    o0 *= gv.x / (1.0f + expf(-gv.x));
                    o1 *= gv.y / (1.0f + expf(-gv.y));
                    uint32_t h, l;
                    split_h2(o0, o1, h, l);
                    const size_t wi = (ro1 + c) >> 1;
                    CH[wi] = h; CL[wi] = l;
                } else if (MODE == 2) {
                    atomicAdd(C + ro1 + c, o0);
                    atomicAdd(C + ro1 + c + 1, o1);
                } else {
                    *(float2*)(C + ro1 + c) = make_float2(o0, o1);
                }
            }
        }
    }
}

// ---------------------------------------------------------------------------
// Launch
// ---------------------------------------------------------------------------
extern "C" void kernel_launch(void* const* d_in, const int* in_sizes, int n_in,
                              void* d_out, int out_size) {
    const float* x  = (const float*)d_in[0];
    const float* rw = (const float*)d_in[1];
    const float* eg = (const float*)d_in[2];
    const float* eu = (const float*)d_in[3];
    const float* ed = (const float*)d_in[4];
    const float* sg = (const float*)d_in[5];
    const float* su = (const float*)d_in[6];
    const float* sd = (const float*)d_in[7];
    float* out = (float*)d_out;

#define SYM(p, s) void* p; cudaGetSymbolAddress(&p, s)
    SYM(p_gate_s, g_gate_s); SYM(p_gate_r, g_gate_r);
    SYM(p_xh, g_xh);   SYM(p_xl, g_xl);
    SYM(p_sgh, g_sgh); SYM(p_sgl, g_sgl);
    SYM(p_suh, g_suh); SYM(p_sul, g_sul);
    SYM(p_sdh, g_sdh); SYM(p_sdl, g_sdl);
    SYM(p_egh, g_egh); SYM(p_egl, g_egl);
    SYM(p_euh, g_euh); SYM(p_eul, g_eul);
    SYM(p_edh, g_edh); SYM(p_edl, g_edl);
    SYM(p_ish, g_ish); SYM(p_isl, g_isl);
    SYM(p_irh, g_irh); SYM(p_irl, g_irl);
#undef SYM

    cudaFuncSetAttribute(tgemm_kernel<0, 0>,
                         cudaFuncAttributeMaxDynamicSharedMemorySize, SMEM_DYN);
    cudaFuncSetAttribute(tgemm_kernel<0, 1>,
                         cudaFuncAttributeMaxDynamicSharedMemorySize, SMEM_DYN);
    cudaFuncSetAttribute(tgemm_kernel<1, 0>,
                         cudaFuncAttributeMaxDynamicSharedMemorySize, SMEM_DYN);
    cudaFuncSetAttribute(tgemm_kernel<1, 1>,
                         cudaFuncAttributeMaxDynamicSharedMemorySize, SMEM_DYN);
    cudaFuncSetAttribute(tgemm_kernel<2, 0>,
                         cudaFuncAttributeMaxDynamicSharedMemorySize, SMEM_DYN);

    zero_counts_kernel<<<1, 32>>>();
    router_kernel<<<T_TOK / 4, 128>>>(x, rw);

    split_contig_kernel<<<(T_TOK * HID / 2 / 4) / 256, 256>>>(
        x, (uint32_t*)p_xh, (uint32_t*)p_xl, T_TOK * HID / 2);
    split_strided_kernel<<<(HID / 2 * FS / 4) / 256, 256>>>(
        sg, (uint32_t*)p_sgh, (uint32_t*)p_sgl, HID / 2 * FS, FS);
    split_strided_kernel<<<(HID / 2 * FS / 4) / 256, 256>>>(
        su, (uint32_t*)p_suh, (uint32_t*)p_sul, HID / 2 * FS, FS);
    split_strided_kernel<<<(FS / 2 * HID / 4) / 256, 256>>>(
        sd, (uint32_t*)p_sdh, (uint32_t*)p_sdl, FS / 2 * HID, HID);
    split_strided_kernel<<<(NE * HID / 2 * FE / 4) / 256, 256>>>(
        eg, (uint32_t*)p_egh, (uint32_t*)p_egl, NE * HID / 2 * FE, FE);
    split_strided_kernel<<<(NE * HID / 2 * FE / 4) / 256, 256>>>(
        eu, (uint32_t*)p_euh, (uint32_t*)p_eul, NE * HID / 2 * FE, FE);
    split_strided_kernel<<<(NE * FE / 2 * HID / 4) / 256, 256>>>(
        ed, (uint32_t*)p_edh, (uint32_t*)p_edl, NE * FE / 2 * HID, HID);

    // Shared expert: gate -> (up, silu fused, split-write) -> down (writes out)
    tgemm_kernel<0, 0><<<dim3(FS / BN, T_TOK / BM, 1), 256, SMEM_DYN>>>(
        (const uint32_t*)p_xh, (const uint32_t*)p_xl,
        (const uint32_t*)p_sgh, (const uint32_t*)p_sgl,
        (float*)p_gate_s, nullptr, nullptr, nullptr, T_TOK, FS, HID);
    tgemm_kernel<0, 1><<<dim3(FS / BN, T_TOK / BM, 1), 256, SMEM_DYN>>>(
        (const uint32_t*)p_xh, (const uint32_t*)p_xl,
        (const uint32_t*)p_suh, (const uint32_t*)p_sul,
        nullptr, (uint32_t*)p_ish, (uint32_t*)p_isl,
        (const float*)p_gate_s, T_TOK, FS, HID);
    tgemm_kernel<0, 0><<<dim3(HID / BN, T_TOK / BM, 1), 256, SMEM_DYN>>>(
        (const uint32_t*)p_ish, (const uint32_t*)p_isl,
        (const uint32_t*)p_sdh, (const uint32_t*)p_sdl,
        out, nullptr, nullptr, nullptr, T_TOK, HID, FS);

    // Routed experts: gate -> (up, silu fused) -> down (atomicAdd into out)
    tgemm_kernel<1, 0><<<dim3(FE / BN, T_TOK / BM, NE), 256, SMEM_DYN>>>(
        (const uint32_t*)p_xh, (const uint32_t*)p_xl,
        (const uint32_t*)p_egh, (const uint32_t*)p_egl,
        (float*)p_gate_r, nullptr, nullptr, nullptr, 0, FE, HID);
    tgemm_kernel<1, 1><<<dim3(FE / BN, T_TOK / BM, NE), 256, SMEM_DYN>>>(
        (const uint32_t*)p_xh, (const uint32_t*)p_xl,
        (const uint32_t*)p_euh, (const uint32_t*)p_eul,
        nullptr, (uint32_t*)p_irh, (uint32_t*)p_irl,
        (const float*)p_gate_r, 0, FE, HID);
    tgemm_kernel<2, 0><<<dim3(HID / BN, T_TOK / BM, NE), 256, SMEM_DYN>>>(
        (const uint32_t*)p_irh, (const uint32_t*)p_irl,
        (const uint32_t*)p_edh, (const uint32_t*)p_edl,
        out, nullptr, nullptr, nullptr, 0, HID, FE);
}